// round 4
// baseline (speedup 1.0000x reference)
#include <cuda_runtime.h>
#include <cuda_bf16.h>
#include <cstdint>

// Problem constants
#define B_  4
#define LQ  1024
#define LKV 4096
#define CQ  512
#define CKV 512
#define E_  512
#define NH  8
#define HD  64

// Scratch (device globals — no allocation allowed)
// Split-bf16 planes: x = hi + lo (+ ~2^-18 rel residual)
__device__ __nv_bfloat16 g_Qhi [B_ * NH * LQ  * HD];  // [b,h,q,d], pre-scaled
__device__ __nv_bfloat16 g_Qlo [B_ * NH * LQ  * HD];
__device__ __nv_bfloat16 g_Khi [B_ * NH * LKV * HD];  // [b,h,k,d]
__device__ __nv_bfloat16 g_Klo [B_ * NH * LKV * HD];
__device__ __nv_bfloat16 g_Vthi[B_ * NH * HD * LKV];  // [b,h,d,k] (transposed)
__device__ __nv_bfloat16 g_Vtlo[B_ * NH * HD * LKV];
__device__ float g_ctx[B_ * LQ * E_];                 // [b,q,(h,d)] fp32

// ---------------------------------------------------------------------------
// helpers
// ---------------------------------------------------------------------------
__device__ __forceinline__ uint32_t smem_u32(const void* p) {
    uint32_t a;
    asm("{ .reg .u64 t; cvta.to.shared.u64 t, %1; cvt.u32.u64 %0, t; }"
        : "=r"(a) : "l"(p));
    return a;
}

__device__ __forceinline__ void mma_bf16(float c[4], const uint32_t a[4],
                                         uint32_t b0, uint32_t b1)
{
    asm volatile(
        "mma.sync.aligned.m16n8k16.row.col.f32.bf16.bf16.f32 "
        "{%0,%1,%2,%3}, {%4,%5,%6,%7}, {%8,%9}, {%0,%1,%2,%3};\n"
        : "+f"(c[0]), "+f"(c[1]), "+f"(c[2]), "+f"(c[3])
        : "r"(a[0]), "r"(a[1]), "r"(a[2]), "r"(a[3]), "r"(b0), "r"(b1));
}

__device__ __forceinline__ uint32_t pack_hi(float v0, float v1,
                                            float& r0, float& r1)
{
    __nv_bfloat162 h = __floats2bfloat162_rn(v0, v1);
    r0 = v0 - __low2float(h);
    r1 = v1 - __high2float(h);
    return *(uint32_t*)&h;
}
__device__ __forceinline__ uint32_t pack_bf2(float v0, float v1)
{
    __nv_bfloat162 h = __floats2bfloat162_rn(v0, v1);
    return *(uint32_t*)&h;
}

// ---------------------------------------------------------------------------
// SGEMM projections (SIMT fp32, exact math) — BM=64, BN=64, BK=16, 256 thr
// ---------------------------------------------------------------------------
#define BM 64
#define BN 64
#define BK 16

__global__ __launch_bounds__(256) void qproj_kernel(
    const float* __restrict__ X, const float* __restrict__ W,
    const float* __restrict__ bias)
{
    const int K = CQ, N = E_;
    __shared__ float As[BK][BM + 1];
    __shared__ float Bs[BK][BN];
    const int m0 = blockIdx.y * BM, n0 = blockIdx.x * BN;
    const int tid = threadIdx.x;
    const int tx = tid & 15, ty = tid >> 4;
    float acc[4][4];
    #pragma unroll
    for (int i = 0; i < 4; i++)
        #pragma unroll
        for (int j = 0; j < 4; j++) acc[i][j] = 0.f;
    for (int k0 = 0; k0 < K; k0 += BK) {
        #pragma unroll
        for (int i = 0; i < 4; i++) {
            int idx = tid + i * 256;
            As[idx % BK][idx / BK] = X[(m0 + idx / BK) * K + k0 + idx % BK];
        }
        #pragma unroll
        for (int i = 0; i < 4; i++) {
            int idx = tid + i * 256;
            Bs[idx / BN][idx % BN] = W[(k0 + idx / BN) * N + n0 + idx % BN];
        }
        __syncthreads();
        #pragma unroll
        for (int kk = 0; kk < BK; kk++) {
            float a[4], b[4];
            #pragma unroll
            for (int i = 0; i < 4; i++) a[i] = As[kk][ty * 4 + i];
            #pragma unroll
            for (int j = 0; j < 4; j++) b[j] = Bs[kk][tx * 4 + j];
            #pragma unroll
            for (int i = 0; i < 4; i++)
                #pragma unroll
                for (int j = 0; j < 4; j++) acc[i][j] += a[i] * b[j];
        }
        __syncthreads();
    }
    const float scale = 0.125f;   // 64^-0.5
    const int h = n0 >> 6;
    #pragma unroll
    for (int i = 0; i < 4; i++) {
        int m = m0 + ty * 4 + i;
        int b = m >> 10, q = m & 1023;
        size_t ro = ((size_t)(b * NH + h) * LQ + q) * HD;
        #pragma unroll
        for (int jp = 0; jp < 2; jp++) {
            int d = tx * 4 + jp * 2;
            float v0 = (acc[i][jp * 2]     + bias[n0 + d])     * scale;
            float v1 = (acc[i][jp * 2 + 1] + bias[n0 + d + 1]) * scale;
            float r0, r1;
            uint32_t hv = pack_hi(v0, v1, r0, r1);
            *(uint32_t*)(g_Qhi + ro + d) = hv;
            *(uint32_t*)(g_Qlo + ro + d) = pack_bf2(r0, r1);
        }
    }
}

__global__ __launch_bounds__(256) void kvproj_kernel(
    const float* __restrict__ X, const float* __restrict__ W,
    const float* __restrict__ bias)
{
    const int K = CKV, N = 2 * E_;
    __shared__ float As[BK][BM + 1];
    __shared__ float Bs[BK][BN];
    __shared__ float Tr[64][65];     // V-tile transpose buffer
    const int m0 = blockIdx.y * BM, n0 = blockIdx.x * BN;
    const int tid = threadIdx.x;
    const int tx = tid & 15, ty = tid >> 4;
    float acc[4][4];
    #pragma unroll
    for (int i = 0; i < 4; i++)
        #pragma unroll
        for (int j = 0; j < 4; j++) acc[i][j] = 0.f;
    for (int k0 = 0; k0 < K; k0 += BK) {
        #pragma unroll
        for (int i = 0; i < 4; i++) {
            int idx = tid + i * 256;
            As[idx % BK][idx / BK] = X[(m0 + idx / BK) * K + k0 + idx % BK];
        }
        #pragma unroll
        for (int i = 0; i < 4; i++) {
            int idx = tid + i * 256;
            Bs[idx / BN][idx % BN] = W[(k0 + idx / BN) * N + n0 + idx % BN];
        }
        __syncthreads();
        #pragma unroll
        for (int kk = 0; kk < BK; kk++) {
            float a[4], b[4];
            #pragma unroll
            for (int i = 0; i < 4; i++) a[i] = As[kk][ty * 4 + i];
            #pragma unroll
            for (int j = 0; j < 4; j++) b[j] = Bs[kk][tx * 4 + j];
            #pragma unroll
            for (int i = 0; i < 4; i++)
                #pragma unroll
                for (int j = 0; j < 4; j++) acc[i][j] += a[i] * b[j];
        }
        __syncthreads();
    }

    const int bb = m0 >> 12;            // batch (tile fits in one batch)
    if (n0 < 512) {
        // ---- K half: write [b,h,key,d] hi/lo planes, d-pairs packed ----
        const int h = n0 >> 6;
        #pragma unroll
        for (int i = 0; i < 4; i++) {
            int m = m0 + ty * 4 + i;
            int key = m & 4095;
            size_t ro = ((size_t)(bb * NH + h) * LKV + key) * HD;
            #pragma unroll
            for (int jp = 0; jp < 2; jp++) {
                int d = tx * 4 + jp * 2;
                float v0 = acc[i][jp * 2]     + bias[n0 + d];
                float v1 = acc[i][jp * 2 + 1] + bias[n0 + d + 1];
                float r0, r1;
                uint32_t hv = pack_hi(v0, v1, r0, r1);
                *(uint32_t*)(g_Khi + ro + d) = hv;
                *(uint32_t*)(g_Klo + ro + d) = pack_bf2(r0, r1);
            }
        }
    } else {
        // ---- V half: transpose in smem, write [b,h,d,key] hi/lo planes ----
        const int h = (n0 >> 6) & 7;
        const int key0 = m0 & 4095;
        #pragma unroll
        for (int i = 0; i < 4; i++)
            #pragma unroll
            for (int j = 0; j < 4; j++)
                Tr[tx * 4 + j][ty * 4 + i] = acc[i][j] + bias[n0 + tx * 4 + j];
        __syncthreads();
        #pragma unroll
        for (int it = 0; it < 8; it++) {
            int idx = tid + it * 256;     // 0..2047
            int d = idx >> 5, kp = (idx & 31) * 2;
            float v0 = Tr[d][kp], v1 = Tr[d][kp + 1];
            float r0, r1;
            uint32_t hv = pack_hi(v0, v1, r0, r1);
            size_t ro = ((size_t)(bb * NH + h) * HD + d) * LKV + key0 + kp;
            *(uint32_t*)(g_Vthi + ro) = hv;
            *(uint32_t*)(g_Vtlo + ro) = pack_bf2(r0, r1);
        }
    }
}

// ---------------------------------------------------------------------------
// Attention: split-bf16 3-term mma.sync flash kernel
// CTA = 128 thr (4 warps) x 64 queries x one (b,h); 64-key tiles,
// cp.async double-buffered. Fixed stabilizer exp(s-8), no online max.
// ---------------------------------------------------------------------------
#define RS    144                 // smem row stride bytes (72 bf16)
#define PL    (64 * RS)           // one 64-row plane = 9216 B
#define STAGE (4 * PL)            // Khi,Klo,Vhi,Vlo
#define SMEM_ATTN (2 * STAGE + 2 * PL)   // + Phi,Plo = 92160 B

__device__ __forceinline__ void load_tile(
    uint32_t sdst,
    const __nv_bfloat16* Khi, const __nv_bfloat16* Klo,
    const __nv_bfloat16* Vhi, const __nv_bfloat16* Vlo,
    int t, int tid)
{
    #pragma unroll
    for (int i = 0; i < 16; i++) {
        int c = tid + i * 128;            // 0..2047 chunks of 16B
        int p = c >> 9;                   // plane (compile-time per i)
        int cc = c & 511, row = cc >> 3, c16 = cc & 7;
        uint32_t dst = sdst + p * PL + row * RS + c16 * 16;
        const __nv_bfloat16* src;
        if (p == 0)      src = Khi + (size_t)(t * 64 + row) * HD + c16 * 8;
        else if (p == 1) src = Klo + (size_t)(t * 64 + row) * HD + c16 * 8;
        else if (p == 2) src = Vhi + (size_t)row * LKV + t * 64 + c16 * 8;
        else             src = Vlo + (size_t)row * LKV + t * 64 + c16 * 8;
        asm volatile("cp.async.cg.shared.global [%0], [%1], 16;"
                     :: "r"(dst), "l"(src));
    }
}

__global__ __launch_bounds__(128) void attn_kernel(
    const float* __restrict__ pos, const int* __restrict__ mask)
{
    extern __shared__ __align__(16) char sm[];
    const int qt = blockIdx.x, h = blockIdx.y, b = blockIdx.z;
    const int tid = threadIdx.x, warp = tid >> 5, lane = tid & 31;
    const int g = lane >> 2, qd = lane & 3;
    const int q0 = qt * 64;
    const uint32_t smb = smem_u32(sm);
    char* Ph = sm + 2 * STAGE;
    char* Pl = Ph + PL;

    const size_t bh = (size_t)(b * NH + h);
    const __nv_bfloat16* Khi = g_Khi + bh * LKV * HD;
    const __nv_bfloat16* Klo = g_Klo + bh * LKV * HD;
    const __nv_bfloat16* Vhi = g_Vthi + bh * HD * LKV;
    const __nv_bfloat16* Vlo = g_Vtlo + bh * HD * LKV;

    // prefetch tile 0 into stage 0
    load_tile(smb, Khi, Klo, Vhi, Vlo, 0, tid);
    asm volatile("cp.async.commit_group;" ::: "memory");

    // Q fragments (hi/lo), loaded once: rows 16*warp+g (+8)
    uint32_t Qh[4][4], Ql[4][4];
    {
        const __nv_bfloat16* qh = g_Qhi + bh * LQ * HD;
        const __nv_bfloat16* ql = g_Qlo + bh * LQ * HD;
        size_t r0 = (size_t)(q0 + 16 * warp + g) * HD;
        size_t r1 = r0 + 8 * HD;
        #pragma unroll
        for (int s = 0; s < 4; s++) {
            int c = s * 16 + qd * 2;
            Qh[s][0] = *(const uint32_t*)(qh + r0 + c);
            Qh[s][1] = *(const uint32_t*)(qh + r1 + c);
            Qh[s][2] = *(const uint32_t*)(qh + r0 + c + 8);
            Qh[s][3] = *(const uint32_t*)(qh + r1 + c + 8);
            Ql[s][0] = *(const uint32_t*)(ql + r0 + c);
            Ql[s][1] = *(const uint32_t*)(ql + r1 + c);
            Ql[s][2] = *(const uint32_t*)(ql + r0 + c + 8);
            Ql[s][3] = *(const uint32_t*)(ql + r1 + c + 8);
        }
    }

    float O[8][4];
    #pragma unroll
    for (int nt = 0; nt < 8; nt++)
        #pragma unroll
        for (int j = 0; j < 4; j++) O[nt][j] = 0.f;
    float ls0 = 0.f, ls1 = 0.f;

    const float* pr0 = pos + (size_t)(h * LQ + q0 + 16 * warp + g) * LKV;
    const float* pr1 = pr0 + (size_t)8 * LKV;
    const int prow = (16 * warp + g) * RS;

    for (int t = 0; t < 64; t++) {
        char* cur = sm + (t & 1) * STAGE;
        __syncthreads();   // everyone done with buffer (t+1)&1 from tile t-1
        if (t < 63) {
            load_tile(smb + ((t + 1) & 1) * STAGE, Khi, Klo, Vhi, Vlo, t + 1, tid);
            asm volatile("cp.async.commit_group;" ::: "memory");
            asm volatile("cp.async.wait_group 1;" ::: "memory");
        } else {
            asm volatile("cp.async.wait_group 0;" ::: "memory");
        }
        __syncthreads();   // tile t visible to all warps

        // ---- S = Q K^T (3-term split) ----
        float S[8][4];
        #pragma unroll
        for (int nt = 0; nt < 8; nt++)
            #pragma unroll
            for (int j = 0; j < 4; j++) S[nt][j] = 0.f;
        const char* Kh = cur;
        const char* Kl = cur + PL;
        #pragma unroll
        for (int s = 0; s < 4; s++) {
            #pragma unroll
            for (int nt = 0; nt < 8; nt++) {
                int ko = (nt * 8 + g) * RS + (s * 16 + qd * 2) * 2;
                uint32_t bh0 = *(const uint32_t*)(Kh + ko);
                uint32_t bh1 = *(const uint32_t*)(Kh + ko + 16);
                uint32_t bl0 = *(const uint32_t*)(Kl + ko);
                uint32_t bl1 = *(const uint32_t*)(Kl + ko + 16);
                mma_bf16(S[nt], Qh[s], bh0, bh1);
                mma_bf16(S[nt], Ql[s], bh0, bh1);
                mma_bf16(S[nt], Qh[s], bl0, bl1);
            }
        }

        // ---- softmax numerators -> P planes (warp-private rows) ----
        #pragma unroll
        for (int nt = 0; nt < 8; nt++) {
            int colg = t * 64 + nt * 8 + qd * 2;
            float2 p0 = *(const float2*)(pr0 + colg);
            float2 p1 = *(const float2*)(pr1 + colg);
            float e0 = __expf(S[nt][0] + p0.x - 8.f);
            float e1 = __expf(S[nt][1] + p0.y - 8.f);
            float e2 = __expf(S[nt][2] + p1.x - 8.f);
            float e3 = __expf(S[nt][3] + p1.y - 8.f);
            ls0 += e0 + e1;
            ls1 += e2 + e3;
            float r0, r1, r2, r3;
            uint32_t h01 = pack_hi(e0, e1, r0, r1);
            uint32_t h23 = pack_hi(e2, e3, r2, r3);
            int po = prow + (nt * 8 + qd * 2) * 2;
            *(uint32_t*)(Ph + po)            = h01;
            *(uint32_t*)(Ph + po + 8 * RS)   = h23;
            *(uint32_t*)(Pl + po)            = pack_bf2(r0, r1);
            *(uint32_t*)(Pl + po + 8 * RS)   = pack_bf2(r2, r3);
        }
        __syncwarp();

        // ---- O += P V (3-term split) ----
        const char* Vh = cur + 2 * PL;
        const char* Vl = cur + 3 * PL;
        #pragma unroll
        for (int s = 0; s < 4; s++) {
            uint32_t ah[4], al[4];
            int base = prow + (s * 16 + qd * 2) * 2;
            ah[0] = *(const uint32_t*)(Ph + base);
            ah[1] = *(const uint32_t*)(Ph + base + 8 * RS);
            ah[2] = *(const uint32_t*)(Ph + base + 16);
            ah[3] = *(const uint32_t*)(Ph + base + 8 * RS + 16);
            al[0] = *(const uint32_t*)(Pl + base);
            al[1] = *(const uint32_t*)(Pl + base + 8 * RS);
            al[2] = *(const uint32_t*)(Pl + base + 16);
            al[3] = *(const uint32_t*)(Pl + base + 8 * RS + 16);
            #pragma unroll
            for (int nt = 0; nt < 8; nt++) {
                int vo = (nt * 8 + g) * RS + (s * 16 + qd * 2) * 2;
                uint32_t bh0 = *(const uint32_t*)(Vh + vo);
                uint32_t bh1 = *(const uint32_t*)(Vh + vo + 16);
                uint32_t bl0 = *(const uint32_t*)(Vl + vo);
                uint32_t bl1 = *(const uint32_t*)(Vl + vo + 16);
                mma_bf16(O[nt], ah, bh0, bh1);
                mma_bf16(O[nt], al, bh0, bh1);
                mma_bf16(O[nt], ah, bl0, bl1);
            }
        }
    }

    // ---- epilogue ----
    ls0 += __shfl_xor_sync(0xffffffffu, ls0, 1);
    ls0 += __shfl_xor_sync(0xffffffffu, ls0, 2);
    ls1 += __shfl_xor_sync(0xffffffffu, ls1, 1);
    ls1 += __shfl_xor_sync(0xffffffffu, ls1, 2);

    const int row0 = 16 * warp + g;
    const int mk0 = mask[b * LQ + q0 + row0];
    const int mk1 = mask[b * LQ + q0 + row0 + 8];
    const float inv0 = (mk0 != 0 && ls0 > 0.f) ? (1.f / ls0) : 0.f;
    const float inv1 = (mk1 != 0 && ls1 > 0.f) ? (1.f / ls1) : 0.f;

    float* c0 = g_ctx + (size_t)(b * LQ + q0 + row0) * E_ + h * HD;
    float* c1 = c0 + (size_t)8 * E_;
    #pragma unroll
    for (int nt = 0; nt < 8; nt++) {
        *(float2*)(c0 + nt * 8 + qd * 2) = make_float2(O[nt][0] * inv0, O[nt][1] * inv0);
        *(float2*)(c1 + nt * 8 + qd * 2) = make_float2(O[nt][2] * inv1, O[nt][3] * inv1);
    }
}

// ----------------------- output projection (SIMT fp32) ---------------------
__global__ __launch_bounds__(256) void oproj_kernel(
    const float* __restrict__ W, const float* __restrict__ bias,
    float* __restrict__ out)
{
    const int K = E_, N = E_;
    __shared__ float As[BK][BM + 1];
    __shared__ float Bs[BK][BN];
    const int m0 = blockIdx.y * BM, n0 = blockIdx.x * BN;
    const int tid = threadIdx.x;
    const int tx = tid & 15, ty = tid >> 4;
    float acc[4][4];
    #pragma unroll
    for (int i = 0; i < 4; i++)
        #pragma unroll
        for (int j = 0; j < 4; j++) acc[i][j] = 0.f;
    for (int k0 = 0; k0 < K; k0 += BK) {
        #pragma unroll
        for (int i = 0; i < 4; i++) {
            int idx = tid + i * 256;
            As[idx % BK][idx / BK] = g_ctx[(size_t)(m0 + idx / BK) * K + k0 + idx % BK];
        }
        #pragma unroll
        for (int i = 0; i < 4; i++) {
            int idx = tid + i * 256;
            Bs[idx / BN][idx % BN] = W[(k0 + idx / BN) * N + n0 + idx % BN];
        }
        __syncthreads();
        #pragma unroll
        for (int kk = 0; kk < BK; kk++) {
            float a[4], b[4];
            #pragma unroll
            for (int i = 0; i < 4; i++) a[i] = As[kk][ty * 4 + i];
            #pragma unroll
            for (int j = 0; j < 4; j++) b[j] = Bs[kk][tx * 4 + j];
            #pragma unroll
            for (int i = 0; i < 4; i++)
                #pragma unroll
                for (int j = 0; j < 4; j++) acc[i][j] += a[i] * b[j];
        }
        __syncthreads();
    }
    #pragma unroll
    for (int i = 0; i < 4; i++) {
        int m = m0 + ty * 4 + i;
        #pragma unroll
        for (int j = 0; j < 4; j++) {
            int n = n0 + tx * 4 + j;
            out[(size_t)m * N + n] = acc[i][j] + bias[n];
        }
    }
}

// ---------------------------------------------------------------------------
extern "C" void kernel_launch(void* const* d_in, const int* in_sizes, int n_in,
                              void* d_out, int out_size)
{
    const float* Xq   = (const float*)d_in[0];
    const float* Xkv  = (const float*)d_in[1];
    const int*   mask = (const int*)  d_in[2];
    const float* Wq   = (const float*)d_in[3];
    const float* bq   = (const float*)d_in[4];
    const float* Wkv  = (const float*)d_in[5];
    const float* bkv  = (const float*)d_in[6];
    const float* Wp   = (const float*)d_in[7];
    const float* bp   = (const float*)d_in[8];
    const float* pos  = (const float*)d_in[9];
    float* out = (float*)d_out;

    static int smem_set = 0;
    if (!smem_set) {
        cudaFuncSetAttribute(attn_kernel,
                             cudaFuncAttributeMaxDynamicSharedMemorySize,
                             SMEM_ATTN);
        smem_set = 1;
    }

    qproj_kernel<<<dim3(E_ / BN, (B_ * LQ) / BM), 256>>>(Xq, Wq, bq);
    kvproj_kernel<<<dim3((2 * E_) / BN, (B_ * LKV) / BM), 256>>>(Xkv, Wkv, bkv);
    attn_kernel<<<dim3(LQ / 64, NH, B_), 128, SMEM_ATTN>>>(pos, mask);
    oproj_kernel<<<dim3(E_ / BN, (B_ * LQ) / BM), 256>>>(Wp, bp, out);
}

// round 5
// speedup vs baseline: 1.5486x; 1.5486x over previous
#include <cuda_runtime.h>
#include <cuda_bf16.h>
#include <cstdint>

// Problem constants
#define B_  4
#define LQ  1024
#define LKV 4096
#define CQ  512
#define CKV 512
#define E_  512
#define NH  8
#define HD  64

// Scratch (device globals — no allocation allowed)
__device__ __nv_bfloat16 g_Qhi [B_ * NH * LQ  * HD];
__device__ __nv_bfloat16 g_Qlo [B_ * NH * LQ  * HD];
__device__ __nv_bfloat16 g_Khi [B_ * NH * LKV * HD];
__device__ __nv_bfloat16 g_Klo [B_ * NH * LKV * HD];
__device__ __nv_bfloat16 g_Vthi[B_ * NH * HD * LKV];  // [b,h,d,k]
__device__ __nv_bfloat16 g_Vtlo[B_ * NH * HD * LKV];
__device__ float g_ctx[B_ * LQ * E_];

// ---------------------------------------------------------------------------
// helpers
// ---------------------------------------------------------------------------
__device__ __forceinline__ uint32_t smem_u32(const void* p) {
    uint32_t a;
    asm("{ .reg .u64 t; cvta.to.shared.u64 t, %1; cvt.u32.u64 %0, t; }"
        : "=r"(a) : "l"(p));
    return a;
}
__device__ __forceinline__ void mma_bf16(float c[4], const uint32_t a[4],
                                         uint32_t b0, uint32_t b1)
{
    asm volatile(
        "mma.sync.aligned.m16n8k16.row.col.f32.bf16.bf16.f32 "
        "{%0,%1,%2,%3}, {%4,%5,%6,%7}, {%8,%9}, {%0,%1,%2,%3};\n"
        : "+f"(c[0]), "+f"(c[1]), "+f"(c[2]), "+f"(c[3])
        : "r"(a[0]), "r"(a[1]), "r"(a[2]), "r"(a[3]), "r"(b0), "r"(b1));
}
__device__ __forceinline__ uint32_t pack_hi(float v0, float v1,
                                            float& r0, float& r1)
{
    __nv_bfloat162 h = __floats2bfloat162_rn(v0, v1);
    r0 = v0 - __low2float(h);
    r1 = v1 - __high2float(h);
    return *(uint32_t*)&h;
}
__device__ __forceinline__ uint32_t pack_bf2(float v0, float v1)
{
    __nv_bfloat162 h = __floats2bfloat162_rn(v0, v1);
    return *(uint32_t*)&h;
}

// ---------------------------------------------------------------------------
// SGEMM core: BM=128, BN=64, BK=16, 256 threads, 8x4 microtile, vectorized
// ---------------------------------------------------------------------------
#define BM 128
#define BN 64
#define BK 16

__device__ __forceinline__ void gemm_core(
    const float* __restrict__ X, const float* __restrict__ W,
    int K, int N, int m0, int n0, int tid,
    float (&As)[BK][BM + 4], float (&Bs)[BK][BN], float (&acc)[8][4])
{
    const int tx = tid & 15, ty = tid >> 4;
    #pragma unroll
    for (int i = 0; i < 8; i++)
        #pragma unroll
        for (int j = 0; j < 4; j++) acc[i][j] = 0.f;

    for (int k0 = 0; k0 < K; k0 += BK) {
        // A tile 128x16: 512 float4 chunks, transpose into As[k][m]
        #pragma unroll
        for (int i = 0; i < 2; i++) {
            int c = tid + i * 256;
            int row = c >> 2, kq = c & 3;
            float4 v = *(const float4*)(X + (size_t)(m0 + row) * K + k0 + kq * 4);
            As[kq * 4 + 0][row] = v.x;
            As[kq * 4 + 1][row] = v.y;
            As[kq * 4 + 2][row] = v.z;
            As[kq * 4 + 3][row] = v.w;
        }
        // B tile 16x64: 256 float4 chunks, direct
        {
            int row = tid >> 4, cq = tid & 15;
            *(float4*)&Bs[row][cq * 4] =
                *(const float4*)(W + (size_t)(k0 + row) * N + n0 + cq * 4);
        }
        __syncthreads();
        #pragma unroll
        for (int kk = 0; kk < BK; kk++) {
            float4 a0 = *(float4*)&As[kk][ty * 8];
            float4 a1 = *(float4*)&As[kk][ty * 8 + 4];
            float4 b  = *(float4*)&Bs[kk][tx * 4];
            float a[8] = {a0.x, a0.y, a0.z, a0.w, a1.x, a1.y, a1.z, a1.w};
            float bb[4] = {b.x, b.y, b.z, b.w};
            #pragma unroll
            for (int i = 0; i < 8; i++)
                #pragma unroll
                for (int j = 0; j < 4; j++) acc[i][j] += a[i] * bb[j];
        }
        __syncthreads();
    }
}

// ----------------------- Kernel 1: Q projection ----------------------------
__global__ __launch_bounds__(256) void qproj_kernel(
    const float* __restrict__ X, const float* __restrict__ W,
    const float* __restrict__ bias)
{
    __shared__ float As[BK][BM + 4];
    __shared__ float Bs[BK][BN];
    const int m0 = blockIdx.y * BM, n0 = blockIdx.x * BN;
    const int tid = threadIdx.x;
    const int tx = tid & 15, ty = tid >> 4;
    float acc[8][4];
    gemm_core(X, W, CQ, E_, m0, n0, tid, As, Bs, acc);

    const float scale = 0.125f;
    const int h = n0 >> 6;
    #pragma unroll
    for (int i = 0; i < 8; i++) {
        int m = m0 + ty * 8 + i;
        int b = m >> 10, q = m & 1023;
        size_t ro = ((size_t)(b * NH + h) * LQ + q) * HD;
        #pragma unroll
        for (int jp = 0; jp < 2; jp++) {
            int d = tx * 4 + jp * 2;
            float v0 = (acc[i][jp * 2]     + bias[n0 + d])     * scale;
            float v1 = (acc[i][jp * 2 + 1] + bias[n0 + d + 1]) * scale;
            float r0, r1;
            uint32_t hv = pack_hi(v0, v1, r0, r1);
            *(uint32_t*)(g_Qhi + ro + d) = hv;
            *(uint32_t*)(g_Qlo + ro + d) = pack_bf2(r0, r1);
        }
    }
}

// ----------------------- Kernel 2: KV projection ---------------------------
__global__ __launch_bounds__(256) void kvproj_kernel(
    const float* __restrict__ X, const float* __restrict__ W,
    const float* __restrict__ bias)
{
    __shared__ float As[BK][BM + 4];
    __shared__ float Bs[BK][BN];
    __shared__ float Tr[64][BM + 1];     // V transpose: [d][key]
    const int m0 = blockIdx.y * BM, n0 = blockIdx.x * BN;
    const int tid = threadIdx.x;
    const int tx = tid & 15, ty = tid >> 4;
    float acc[8][4];
    gemm_core(X, W, CKV, 2 * E_, m0, n0, tid, As, Bs, acc);

    const int bb = m0 >> 12;
    if (n0 < 512) {
        const int h = n0 >> 6;
        #pragma unroll
        for (int i = 0; i < 8; i++) {
            int m = m0 + ty * 8 + i;
            int key = m & 4095;
            size_t ro = ((size_t)(bb * NH + h) * LKV + key) * HD;
            #pragma unroll
            for (int jp = 0; jp < 2; jp++) {
                int d = tx * 4 + jp * 2;
                float v0 = acc[i][jp * 2]     + bias[n0 + d];
                float v1 = acc[i][jp * 2 + 1] + bias[n0 + d + 1];
                float r0, r1;
                uint32_t hv = pack_hi(v0, v1, r0, r1);
                *(uint32_t*)(g_Khi + ro + d) = hv;
                *(uint32_t*)(g_Klo + ro + d) = pack_bf2(r0, r1);
            }
        }
    } else {
        const int h = (n0 >> 6) & 7;
        const int key0 = m0 & 4095;
        #pragma unroll
        for (int i = 0; i < 8; i++)
            #pragma unroll
            for (int j = 0; j < 4; j++)
                Tr[tx * 4 + j][ty * 8 + i] = acc[i][j] + bias[n0 + tx * 4 + j];
        __syncthreads();
        // 64 d-rows x 128 keys -> 4096 key-pairs
        #pragma unroll
        for (int it = 0; it < 16; it++) {
            int idx = tid + it * 256;
            int d = idx >> 6, kp = (idx & 63) * 2;
            float v0 = Tr[d][kp], v1 = Tr[d][kp + 1];
            float r0, r1;
            uint32_t hv = pack_hi(v0, v1, r0, r1);
            size_t ro = ((size_t)(bb * NH + h) * HD + d) * LKV + key0 + kp;
            *(uint32_t*)(g_Vthi + ro) = hv;
            *(uint32_t*)(g_Vtlo + ro) = pack_bf2(r0, r1);
        }
    }
}

// ---------------------------------------------------------------------------
// Attention: split-bf16 3-term mma flash, register-resident P
// CTA = 256 thr (8 warps) x 128 queries x one (b,h); 64-key tiles,
// cp.async double-buffered. Fixed stabilizer exp(s-8), no online max.
// ---------------------------------------------------------------------------
#define RS    144                 // smem row stride bytes (72 bf16)
#define PL    (64 * RS)           // plane = 9216 B
#define STAGE (4 * PL)            // Khi,Klo,Vhi,Vlo = 36864 B
#define SMEM_ATTN (2 * STAGE)     // 73728 B

__device__ __forceinline__ void load_tile(
    uint32_t sdst,
    const __nv_bfloat16* Khi, const __nv_bfloat16* Klo,
    const __nv_bfloat16* Vhi, const __nv_bfloat16* Vlo,
    int t, int tid)
{
    #pragma unroll
    for (int i = 0; i < 8; i++) {
        int c = tid + i * 256;            // 0..2047 chunks of 16B
        int p = i >> 1;                   // plane (compile-time)
        int cc = c & 511, row = cc >> 3, c16 = cc & 7;
        uint32_t dst = sdst + p * PL + row * RS + c16 * 16;
        const __nv_bfloat16* src;
        if (p == 0)      src = Khi + (size_t)(t * 64 + row) * HD + c16 * 8;
        else if (p == 1) src = Klo + (size_t)(t * 64 + row) * HD + c16 * 8;
        else if (p == 2) src = Vhi + (size_t)row * LKV + t * 64 + c16 * 8;
        else             src = Vlo + (size_t)row * LKV + t * 64 + c16 * 8;
        asm volatile("cp.async.cg.shared.global [%0], [%1], 16;"
                     :: "r"(dst), "l"(src));
    }
}

__global__ __launch_bounds__(256, 2) void attn_kernel(
    const float* __restrict__ pos, const int* __restrict__ mask)
{
    extern __shared__ __align__(16) char sm[];
    const int qt = blockIdx.x, h = blockIdx.y, b = blockIdx.z;
    const int tid = threadIdx.x, warp = tid >> 5, lane = tid & 31;
    const int g = lane >> 2, qd = lane & 3;
    const int q0 = qt * 128;
    const uint32_t smb = smem_u32(sm);

    const size_t bh = (size_t)(b * NH + h);
    const __nv_bfloat16* Khi = g_Khi + bh * LKV * HD;
    const __nv_bfloat16* Klo = g_Klo + bh * LKV * HD;
    const __nv_bfloat16* Vhi = g_Vthi + bh * HD * LKV;
    const __nv_bfloat16* Vlo = g_Vtlo + bh * HD * LKV;

    // prefetch tile 0
    load_tile(smb, Khi, Klo, Vhi, Vlo, 0, tid);
    asm volatile("cp.async.commit_group;" ::: "memory");

    // Q fragments (hi/lo): this warp's rows 16*warp+g, +8
    uint32_t Qh[4][4], Ql[4][4];
    {
        const __nv_bfloat16* qh = g_Qhi + bh * LQ * HD;
        const __nv_bfloat16* ql = g_Qlo + bh * LQ * HD;
        size_t r0 = (size_t)(q0 + 16 * warp + g) * HD;
        size_t r1 = r0 + 8 * HD;
        #pragma unroll
        for (int s = 0; s < 4; s++) {
            int c = s * 16 + qd * 2;
            Qh[s][0] = *(const uint32_t*)(qh + r0 + c);
            Qh[s][1] = *(const uint32_t*)(qh + r1 + c);
            Qh[s][2] = *(const uint32_t*)(qh + r0 + c + 8);
            Qh[s][3] = *(const uint32_t*)(qh + r1 + c + 8);
            Ql[s][0] = *(const uint32_t*)(ql + r0 + c);
            Ql[s][1] = *(const uint32_t*)(ql + r1 + c);
            Ql[s][2] = *(const uint32_t*)(ql + r0 + c + 8);
            Ql[s][3] = *(const uint32_t*)(ql + r1 + c + 8);
        }
    }

    float O[8][4];
    #pragma unroll
    for (int nt = 0; nt < 8; nt++)
        #pragma unroll
        for (int j = 0; j < 4; j++) O[nt][j] = 0.f;
    float ls0 = 0.f, ls1 = 0.f;

    const float* pr0 = pos + (size_t)(h * LQ + q0 + 16 * warp + g) * LKV;
    const float* pr1 = pr0 + (size_t)8 * LKV;

    for (int t = 0; t < 64; t++) {
        const char* cur = sm + (t & 1) * STAGE;
        __syncthreads();   // all warps done with buffer (t+1)&1
        if (t < 63) {
            load_tile(smb + ((t + 1) & 1) * STAGE, Khi, Klo, Vhi, Vlo, t + 1, tid);
            asm volatile("cp.async.commit_group;" ::: "memory");
            asm volatile("cp.async.wait_group 1;" ::: "memory");
        } else {
            asm volatile("cp.async.wait_group 0;" ::: "memory");
        }
        __syncthreads();   // tile t visible

        // ---- S = Q K^T (3-term split) ----
        float S[8][4];
        #pragma unroll
        for (int nt = 0; nt < 8; nt++)
            #pragma unroll
            for (int j = 0; j < 4; j++) S[nt][j] = 0.f;
        const char* Kh = cur;
        const char* Kl = cur + PL;
        #pragma unroll
        for (int s = 0; s < 4; s++) {
            #pragma unroll
            for (int nt = 0; nt < 8; nt++) {
                int ko = (nt * 8 + g) * RS + (s * 16 + qd * 2) * 2;
                uint32_t bh0 = *(const uint32_t*)(Kh + ko);
                uint32_t bh1 = *(const uint32_t*)(Kh + ko + 16);
                uint32_t bl0 = *(const uint32_t*)(Kl + ko);
                uint32_t bl1 = *(const uint32_t*)(Kl + ko + 16);
                mma_bf16(S[nt], Qh[s], bh0, bh1);
                mma_bf16(S[nt], Ql[s], bh0, bh1);
                mma_bf16(S[nt], Qh[s], bl0, bl1);
            }
        }

        // ---- exp + pack (register P) fused with PV per k-chunk s ----
        const char* Vh = cur + 2 * PL;
        const char* Vl = cur + 3 * PL;
        #pragma unroll
        for (int s = 0; s < 4; s++) {
            // pos for S[2s] (cols s*16+2qd) and S[2s+1] (cols +8)
            int colg = t * 64 + s * 16 + 2 * qd;
            float2 pa0 = *(const float2*)(pr0 + colg);
            float2 pb0 = *(const float2*)(pr1 + colg);
            float2 pa1 = *(const float2*)(pr0 + colg + 8);
            float2 pb1 = *(const float2*)(pr1 + colg + 8);
            float e00 = __expf(S[2*s][0]   + pa0.x - 8.f);
            float e01 = __expf(S[2*s][1]   + pa0.y - 8.f);
            float e02 = __expf(S[2*s][2]   + pb0.x - 8.f);
            float e03 = __expf(S[2*s][3]   + pb0.y - 8.f);
            float e10 = __expf(S[2*s+1][0] + pa1.x - 8.f);
            float e11 = __expf(S[2*s+1][1] + pa1.y - 8.f);
            float e12 = __expf(S[2*s+1][2] + pb1.x - 8.f);
            float e13 = __expf(S[2*s+1][3] + pb1.y - 8.f);
            ls0 += e00 + e01 + e10 + e11;
            ls1 += e02 + e03 + e12 + e13;
            // A fragments: a0=row g k-lo, a1=row g+8 k-lo, a2=row g k-hi, a3=row g+8 k-hi
            uint32_t ah[4], al[4];
            float r0, r1;
            ah[0] = pack_hi(e00, e01, r0, r1); al[0] = pack_bf2(r0, r1);
            ah[1] = pack_hi(e02, e03, r0, r1); al[1] = pack_bf2(r0, r1);
            ah[2] = pack_hi(e10, e11, r0, r1); al[2] = pack_bf2(r0, r1);
            ah[3] = pack_hi(e12, e13, r0, r1); al[3] = pack_bf2(r0, r1);
            // O += P V for this k-chunk
            #pragma unroll
            for (int nt = 0; nt < 8; nt++) {
                int vo = (nt * 8 + g) * RS + (s * 16 + qd * 2) * 2;
                uint32_t bh0 = *(const uint32_t*)(Vh + vo);
                uint32_t bh1 = *(const uint32_t*)(Vh + vo + 16);
                uint32_t bl0 = *(const uint32_t*)(Vl + vo);
                uint32_t bl1 = *(const uint32_t*)(Vl + vo + 16);
                mma_bf16(O[nt], ah, bh0, bh1);
                mma_bf16(O[nt], al, bh0, bh1);
                mma_bf16(O[nt], ah, bl0, bl1);
            }
        }
    }

    // ---- epilogue ----
    ls0 += __shfl_xor_sync(0xffffffffu, ls0, 1);
    ls0 += __shfl_xor_sync(0xffffffffu, ls0, 2);
    ls1 += __shfl_xor_sync(0xffffffffu, ls1, 1);
    ls1 += __shfl_xor_sync(0xffffffffu, ls1, 2);

    const int row0 = 16 * warp + g;
    const int mk0 = mask[b * LQ + q0 + row0];
    const int mk1 = mask[b * LQ + q0 + row0 + 8];
    const float inv0 = (mk0 != 0 && ls0 > 0.f) ? (1.f / ls0) : 0.f;
    const float inv1 = (mk1 != 0 && ls1 > 0.f) ? (1.f / ls1) : 0.f;

    float* c0 = g_ctx + (size_t)(b * LQ + q0 + row0) * E_ + h * HD;
    float* c1 = c0 + (size_t)8 * E_;
    #pragma unroll
    for (int nt = 0; nt < 8; nt++) {
        *(float2*)(c0 + nt * 8 + qd * 2) = make_float2(O[nt][0] * inv0, O[nt][1] * inv0);
        *(float2*)(c1 + nt * 8 + qd * 2) = make_float2(O[nt][2] * inv1, O[nt][3] * inv1);
    }
}

// ----------------------- Kernel 4: output projection -----------------------
__global__ __launch_bounds__(256) void oproj_kernel(
    const float* __restrict__ W, const float* __restrict__ bias,
    float* __restrict__ out)
{
    __shared__ float As[BK][BM + 4];
    __shared__ float Bs[BK][BN];
    const int m0 = blockIdx.y * BM, n0 = blockIdx.x * BN;
    const int tid = threadIdx.x;
    const int tx = tid & 15, ty = tid >> 4;
    float acc[8][4];
    gemm_core(g_ctx, W, E_, E_, m0, n0, tid, As, Bs, acc);

    #pragma unroll
    for (int i = 0; i < 8; i++) {
        int m = m0 + ty * 8 + i;
        int n = n0 + tx * 4;
        float4 o;
        o.x = acc[i][0] + bias[n];
        o.y = acc[i][1] + bias[n + 1];
        o.z = acc[i][2] + bias[n + 2];
        o.w = acc[i][3] + bias[n + 3];
        *(float4*)(out + (size_t)m * E_ + n) = o;
    }
}

// ---------------------------------------------------------------------------
extern "C" void kernel_launch(void* const* d_in, const int* in_sizes, int n_in,
                              void* d_out, int out_size)
{
    const float* Xq   = (const float*)d_in[0];
    const float* Xkv  = (const float*)d_in[1];
    const int*   mask = (const int*)  d_in[2];
    const float* Wq   = (const float*)d_in[3];
    const float* bq   = (const float*)d_in[4];
    const float* Wkv  = (const float*)d_in[5];
    const float* bkv  = (const float*)d_in[6];
    const float* Wp   = (const float*)d_in[7];
    const float* bp   = (const float*)d_in[8];
    const float* pos  = (const float*)d_in[9];
    float* out = (float*)d_out;

    static int smem_set = 0;
    if (!smem_set) {
        cudaFuncSetAttribute(attn_kernel,
                             cudaFuncAttributeMaxDynamicSharedMemorySize,
                             SMEM_ATTN);
        smem_set = 1;
    }

    qproj_kernel<<<dim3(E_ / BN, (B_ * LQ) / BM), 256>>>(Xq, Wq, bq);
    kvproj_kernel<<<dim3((2 * E_) / BN, (B_ * LKV) / BM), 256>>>(Xkv, Wkv, bkv);
    attn_kernel<<<dim3(LQ / 128, NH, B_), 256, SMEM_ATTN>>>(pos, mask);
    oproj_kernel<<<dim3(E_ / BN, (B_ * LQ) / BM), 256>>>(Wp, bp, out);
}

// round 6
// speedup vs baseline: 2.1673x; 1.3996x over previous
#include <cuda_runtime.h>
#include <cuda_bf16.h>
#include <cstdint>

// Problem constants
#define B_  4
#define LQ  1024
#define LKV 4096
#define CQ  512
#define CKV 512
#define E_  512
#define NH  8
#define HD  64
#define GK  512   // contraction dim of every projection

// ---------------------------------------------------------------------------
// Scratch (device globals — no allocation allowed). All split-bf16 planes.
// ---------------------------------------------------------------------------
__device__ __align__(256) __nv_bfloat16 g_Xqhi [B_ * LQ  * CQ];
__device__ __align__(256) __nv_bfloat16 g_Xqlo [B_ * LQ  * CQ];
__device__ __align__(256) __nv_bfloat16 g_Xkvhi[B_ * LKV * CKV];
__device__ __align__(256) __nv_bfloat16 g_Xkvlo[B_ * LKV * CKV];
__device__ __align__(256) __nv_bfloat16 g_Wqt  [E_ * CQ];        // [N,K] hi
__device__ __align__(256) __nv_bfloat16 g_Wqtl [E_ * CQ];
__device__ __align__(256) __nv_bfloat16 g_Wkvt [2 * E_ * CKV];
__device__ __align__(256) __nv_bfloat16 g_Wkvtl[2 * E_ * CKV];
__device__ __align__(256) __nv_bfloat16 g_Wpt  [E_ * E_];
__device__ __align__(256) __nv_bfloat16 g_Wptl [E_ * E_];
__device__ __align__(256) __nv_bfloat16 g_Qhi [B_ * NH * LQ  * HD];
__device__ __align__(256) __nv_bfloat16 g_Qlo [B_ * NH * LQ  * HD];
__device__ __align__(256) __nv_bfloat16 g_Khi [B_ * NH * LKV * HD];
__device__ __align__(256) __nv_bfloat16 g_Klo [B_ * NH * LKV * HD];
__device__ __align__(256) __nv_bfloat16 g_Vthi[B_ * NH * HD * LKV];  // [b,h,d,k]
__device__ __align__(256) __nv_bfloat16 g_Vtlo[B_ * NH * HD * LKV];
__device__ __align__(256) __nv_bfloat16 g_ctxhi[B_ * LQ * E_];       // [b,q,(h,d)]
__device__ __align__(256) __nv_bfloat16 g_ctxlo[B_ * LQ * E_];

// ---------------------------------------------------------------------------
// helpers
// ---------------------------------------------------------------------------
__device__ __forceinline__ uint32_t smem_u32(const void* p) {
    uint32_t a;
    asm("{ .reg .u64 t; cvta.to.shared.u64 t, %1; cvt.u32.u64 %0, t; }"
        : "=r"(a) : "l"(p));
    return a;
}
__device__ __forceinline__ void mma_bf16(float c[4], const uint32_t a[4],
                                         uint32_t b0, uint32_t b1)
{
    asm volatile(
        "mma.sync.aligned.m16n8k16.row.col.f32.bf16.bf16.f32 "
        "{%0,%1,%2,%3}, {%4,%5,%6,%7}, {%8,%9}, {%0,%1,%2,%3};\n"
        : "+f"(c[0]), "+f"(c[1]), "+f"(c[2]), "+f"(c[3])
        : "r"(a[0]), "r"(a[1]), "r"(a[2]), "r"(a[3]), "r"(b0), "r"(b1));
}
__device__ __forceinline__ uint32_t pack_hi(float v0, float v1,
                                            float& r0, float& r1)
{
    __nv_bfloat162 h = __floats2bfloat162_rn(v0, v1);
    r0 = v0 - __low2float(h);
    r1 = v1 - __high2float(h);
    return *(uint32_t*)&h;
}
__device__ __forceinline__ uint32_t pack_bf2(float v0, float v1)
{
    __nv_bfloat162 h = __floats2bfloat162_rn(v0, v1);
    return *(uint32_t*)&h;
}

// ---------------------------------------------------------------------------
// Prep kernels
// ---------------------------------------------------------------------------
// Elementwise split: fp32 -> bf16 hi/lo planes (float4 vectorized)
__global__ __launch_bounds__(256) void split_kernel(
    const float* __restrict__ src, __nv_bfloat16* __restrict__ hi,
    __nv_bfloat16* __restrict__ lo, int n4)
{
    int i = blockIdx.x * 256 + threadIdx.x;
    if (i >= n4) return;
    float4 v = ((const float4*)src)[i];
    float r0, r1;
    uint32_t h01 = pack_hi(v.x, v.y, r0, r1);
    uint32_t l01 = pack_bf2(r0, r1);
    uint32_t h23 = pack_hi(v.z, v.w, r0, r1);
    uint32_t l23 = pack_bf2(r0, r1);
    ((uint32_t*)hi)[2 * i]     = h01;
    ((uint32_t*)hi)[2 * i + 1] = h23;
    ((uint32_t*)lo)[2 * i]     = l01;
    ((uint32_t*)lo)[2 * i + 1] = l23;
}

// Transpose + split: W [K,N] fp32 -> T [N,K] bf16 hi/lo
__global__ __launch_bounds__(256) void tsplit_kernel(
    const float* __restrict__ W, __nv_bfloat16* __restrict__ Thi,
    __nv_bfloat16* __restrict__ Tlo, int K, int N)
{
    __shared__ float Ts[32][33];
    const int k0 = blockIdx.y * 32, n0 = blockIdx.x * 32;
    const int tx = threadIdx.x & 31, ty = threadIdx.x >> 5;  // ty 0..7
    #pragma unroll
    for (int i = 0; i < 4; i++) {
        int k = ty + i * 8;
        Ts[k][tx] = W[(size_t)(k0 + k) * N + n0 + tx];
    }
    __syncthreads();
    #pragma unroll
    for (int i = 0; i < 4; i++) {
        int nr = ty + i * 8;
        float v = Ts[tx][nr];                 // = W[k0+tx][n0+nr]
        __nv_bfloat16 h = __float2bfloat16_rn(v);
        size_t o = (size_t)(n0 + nr) * K + k0 + tx;
        Thi[o] = h;
        Tlo[o] = __float2bfloat16_rn(v - __bfloat162float(h));
    }
}

// ---------------------------------------------------------------------------
// Split-bf16 mma GEMM core: C[M,N] = A[M,K] * Bt[N,K]^T, K = 512
// CTA: 256 thr / 8 warps, tile 128(M) x 64(N), K-chunks of 64,
// cp.async double-buffered. Warp w owns rows 16w..16w+15. 3-term split.
// ---------------------------------------------------------------------------
#define GRS    144                   // smem row stride bytes (72 bf16)
#define GA_PL  (128 * GRS)           // 18432
#define GB_PL  (64 * GRS)            // 9216
#define GSTAGE (2 * GA_PL + 2 * GB_PL)   // 55296
#define GSMEM  (2 * GSTAGE)          // 110592

__device__ __forceinline__ void gload(
    uint32_t sdst,
    const __nv_bfloat16* Ahi, const __nv_bfloat16* Alo,
    const __nv_bfloat16* Bthi, const __nv_bfloat16* Btlo,
    int m0, int n0, int c, int tid)
{
    #pragma unroll
    for (int i = 0; i < 12; i++) {
        int idx = tid + i * 256;
        uint32_t dst;
        const __nv_bfloat16* src;
        if (i < 8) {                          // A planes (idx 0..2047)
            int p = idx >> 10;
            int r = (idx & 1023) >> 3, c16 = idx & 7;
            dst = sdst + p * GA_PL + r * GRS + c16 * 16;
            src = (p ? Alo : Ahi) + (size_t)(m0 + r) * GK + c * 64 + c16 * 8;
        } else {                              // B planes (idx 2048..3071)
            int j = idx - 2048;
            int p = j >> 9;
            int r = (j & 511) >> 3, c16 = j & 7;
            dst = sdst + 2 * GA_PL + p * GB_PL + r * GRS + c16 * 16;
            src = (p ? Btlo : Bthi) + (size_t)(n0 + r) * GK + c * 64 + c16 * 8;
        }
        asm volatile("cp.async.cg.shared.global [%0], [%1], 16;"
                     :: "r"(dst), "l"(src));
    }
}

__device__ __forceinline__ void gemm_mma_core(
    const __nv_bfloat16* Ahi, const __nv_bfloat16* Alo,
    const __nv_bfloat16* Bthi, const __nv_bfloat16* Btlo,
    int m0, int n0, char* sm, int tid, float (&S)[8][4])
{
    const uint32_t smb = smem_u32(sm);
    const int warp = tid >> 5, lane = tid & 31;
    const int g = lane >> 2, qd = lane & 3;

    #pragma unroll
    for (int nt = 0; nt < 8; nt++)
        #pragma unroll
        for (int j = 0; j < 4; j++) S[nt][j] = 0.f;

    gload(smb, Ahi, Alo, Bthi, Btlo, m0, n0, 0, tid);
    asm volatile("cp.async.commit_group;" ::: "memory");

    for (int c = 0; c < 8; c++) {
        const char* cur = sm + (c & 1) * GSTAGE;
        __syncthreads();
        if (c < 7) {
            gload(smb + ((c + 1) & 1) * GSTAGE, Ahi, Alo, Bthi, Btlo,
                  m0, n0, c + 1, tid);
            asm volatile("cp.async.commit_group;" ::: "memory");
            asm volatile("cp.async.wait_group 1;" ::: "memory");
        } else {
            asm volatile("cp.async.wait_group 0;" ::: "memory");
        }
        __syncthreads();

        const char* Ah = cur;
        const char* Al = cur + GA_PL;
        const char* Bh = cur + 2 * GA_PL;
        const char* Bl = cur + 2 * GA_PL + GB_PL;
        #pragma unroll
        for (int s = 0; s < 4; s++) {
            uint32_t af[4], alf[4];
            int r0o = (16 * warp + g) * GRS + s * 32 + qd * 4;
            int r1o = r0o + 8 * GRS;
            af[0]  = *(const uint32_t*)(Ah + r0o);
            af[1]  = *(const uint32_t*)(Ah + r1o);
            af[2]  = *(const uint32_t*)(Ah + r0o + 16);
            af[3]  = *(const uint32_t*)(Ah + r1o + 16);
            alf[0] = *(const uint32_t*)(Al + r0o);
            alf[1] = *(const uint32_t*)(Al + r1o);
            alf[2] = *(const uint32_t*)(Al + r0o + 16);
            alf[3] = *(const uint32_t*)(Al + r1o + 16);
            #pragma unroll
            for (int nt = 0; nt < 8; nt++) {
                int bo = (nt * 8 + g) * GRS + s * 32 + qd * 4;
                uint32_t bh0 = *(const uint32_t*)(Bh + bo);
                uint32_t bh1 = *(const uint32_t*)(Bh + bo + 16);
                uint32_t bl0 = *(const uint32_t*)(Bl + bo);
                uint32_t bl1 = *(const uint32_t*)(Bl + bo + 16);
                mma_bf16(S[nt], af,  bh0, bh1);
                mma_bf16(S[nt], alf, bh0, bh1);
                mma_bf16(S[nt], af,  bl0, bl1);
            }
        }
    }
}

// ----------------------- Kernel 1: Q projection ----------------------------
__global__ __launch_bounds__(256, 2) void qproj_kernel(
    const float* __restrict__ bias)
{
    extern __shared__ __align__(16) char sm[];
    const int m0 = blockIdx.y * 128, n0 = blockIdx.x * 64;
    const int tid = threadIdx.x, warp = tid >> 5, lane = tid & 31;
    const int g = lane >> 2, qd = lane & 3;
    float S[8][4];
    gemm_mma_core(g_Xqhi, g_Xqlo, g_Wqt, g_Wqtl, m0, n0, sm, tid, S);

    const float scale = 0.125f;
    const int h = n0 >> 6;
    const int r0 = m0 + 16 * warp + g, r1 = r0 + 8;
    const int b0 = r0 >> 10, q0 = r0 & 1023;
    const int b1 = r1 >> 10, q1 = r1 & 1023;
    size_t ro0 = ((size_t)(b0 * NH + h) * LQ + q0) * HD;
    size_t ro1 = ((size_t)(b1 * NH + h) * LQ + q1) * HD;
    #pragma unroll
    for (int nt = 0; nt < 8; nt++) {
        int n = n0 + nt * 8 + qd * 2;
        int d = n & 63;
        float v0 = (S[nt][0] + bias[n])     * scale;
        float v1 = (S[nt][1] + bias[n + 1]) * scale;
        float v2 = (S[nt][2] + bias[n])     * scale;
        float v3 = (S[nt][3] + bias[n + 1]) * scale;
        float r0f, r1f;
        uint32_t h01 = pack_hi(v0, v1, r0f, r1f);
        *(uint32_t*)(g_Qhi + ro0 + d) = h01;
        *(uint32_t*)(g_Qlo + ro0 + d) = pack_bf2(r0f, r1f);
        uint32_t h23 = pack_hi(v2, v3, r0f, r1f);
        *(uint32_t*)(g_Qhi + ro1 + d) = h23;
        *(uint32_t*)(g_Qlo + ro1 + d) = pack_bf2(r0f, r1f);
    }
}

// ----------------------- Kernel 2: KV projection ---------------------------
__global__ __launch_bounds__(256, 2) void kvproj_kernel(
    const float* __restrict__ bias)
{
    extern __shared__ __align__(16) char sm[];
    const int m0 = blockIdx.y * 128, n0 = blockIdx.x * 64;
    const int tid = threadIdx.x, warp = tid >> 5, lane = tid & 31;
    const int g = lane >> 2, qd = lane & 3;
    float S[8][4];
    gemm_mma_core(g_Xkvhi, g_Xkvlo, g_Wkvt, g_Wkvtl, m0, n0, sm, tid, S);

    const int bb = m0 >> 12;
    if (n0 < 512) {
        // K half -> g_Khi/g_Klo [b,h,key,d]
        const int h = n0 >> 6;
        const int k0r = (m0 + 16 * warp + g) & 4095;
        size_t ro0 = ((size_t)(bb * NH + h) * LKV + k0r) * HD;
        size_t ro1 = ro0 + (size_t)8 * HD;
        #pragma unroll
        for (int nt = 0; nt < 8; nt++) {
            int n = n0 + nt * 8 + qd * 2;
            int d = n & 63;
            float v0 = S[nt][0] + bias[n];
            float v1 = S[nt][1] + bias[n + 1];
            float v2 = S[nt][2] + bias[n];
            float v3 = S[nt][3] + bias[n + 1];
            float r0f, r1f;
            uint32_t h01 = pack_hi(v0, v1, r0f, r1f);
            *(uint32_t*)(g_Khi + ro0 + d) = h01;
            *(uint32_t*)(g_Klo + ro0 + d) = pack_bf2(r0f, r1f);
            uint32_t h23 = pack_hi(v2, v3, r0f, r1f);
            *(uint32_t*)(g_Khi + ro1 + d) = h23;
            *(uint32_t*)(g_Klo + ro1 + d) = pack_bf2(r0f, r1f);
        }
    } else {
        // V half: transpose 128key x 64d tile via smem -> g_Vthi/lo [b,h,d,key]
        const int h = (n0 >> 6) & 7;
        const int key0 = m0 & 4095;
        float (*Tr)[132] = (float (*)[132])sm;      // [64 d][128 key + pad]
        __syncthreads();                            // done with gemm smem
        const int kr0 = 16 * warp + g, kr1 = kr0 + 8;
        #pragma unroll
        for (int nt = 0; nt < 8; nt++) {
            int n = n0 + nt * 8 + qd * 2;
            int d = n & 63;
            Tr[d][kr0]     = S[nt][0] + bias[n];
            Tr[d + 1][kr0] = S[nt][1] + bias[n + 1];
            Tr[d][kr1]     = S[nt][2] + bias[n];
            Tr[d + 1][kr1] = S[nt][3] + bias[n + 1];
        }
        __syncthreads();
        #pragma unroll
        for (int it = 0; it < 16; it++) {
            int idx = tid + it * 256;               // 0..4095
            int d = idx >> 6, kp = (idx & 63) * 2;
            float v0 = Tr[d][kp], v1 = Tr[d][kp + 1];
            float r0f, r1f;
            uint32_t hv = pack_hi(v0, v1, r0f, r1f);
            size_t ro = ((size_t)(bb * NH + h) * HD + d) * LKV + key0 + kp;
            *(uint32_t*)(g_Vthi + ro) = hv;
            *(uint32_t*)(g_Vtlo + ro) = pack_bf2(r0f, r1f);
        }
    }
}

// ----------------------- Kernel 4: output projection -----------------------
__global__ __launch_bounds__(256, 2) void oproj_kernel(
    const float* __restrict__ bias, float* __restrict__ out)
{
    extern __shared__ __align__(16) char sm[];
    const int m0 = blockIdx.y * 128, n0 = blockIdx.x * 64;
    const int tid = threadIdx.x, warp = tid >> 5, lane = tid & 31;
    const int g = lane >> 2, qd = lane & 3;
    float S[8][4];
    gemm_mma_core(g_ctxhi, g_ctxlo, g_Wpt, g_Wptl, m0, n0, sm, tid, S);

    const int r0 = m0 + 16 * warp + g, r1 = r0 + 8;
    #pragma unroll
    for (int nt = 0; nt < 8; nt++) {
        int n = n0 + nt * 8 + qd * 2;
        float b0v = bias[n], b1v = bias[n + 1];
        *(float2*)(out + (size_t)r0 * E_ + n) = make_float2(S[nt][0] + b0v, S[nt][1] + b1v);
        *(float2*)(out + (size_t)r1 * E_ + n) = make_float2(S[nt][2] + b0v, S[nt][3] + b1v);
    }
}

// ---------------------------------------------------------------------------
// Attention: split-bf16 3-term mma flash, register-resident P (unchanged from
// R5 except epilogue writes ctx hi/lo planes).
// ---------------------------------------------------------------------------
#define RS    144
#define PL    (64 * RS)
#define STAGE (4 * PL)
#define SMEM_ATTN (2 * STAGE)

__device__ __forceinline__ void load_tile(
    uint32_t sdst,
    const __nv_bfloat16* Khi, const __nv_bfloat16* Klo,
    const __nv_bfloat16* Vhi, const __nv_bfloat16* Vlo,
    int t, int tid)
{
    #pragma unroll
    for (int i = 0; i < 8; i++) {
        int c = tid + i * 256;
        int p = i >> 1;
        int cc = c & 511, row = cc >> 3, c16 = cc & 7;
        uint32_t dst = sdst + p * PL + row * RS + c16 * 16;
        const __nv_bfloat16* src;
        if (p == 0)      src = Khi + (size_t)(t * 64 + row) * HD + c16 * 8;
        else if (p == 1) src = Klo + (size_t)(t * 64 + row) * HD + c16 * 8;
        else if (p == 2) src = Vhi + (size_t)row * LKV + t * 64 + c16 * 8;
        else             src = Vlo + (size_t)row * LKV + t * 64 + c16 * 8;
        asm volatile("cp.async.cg.shared.global [%0], [%1], 16;"
                     :: "r"(dst), "l"(src));
    }
}

__global__ __launch_bounds__(256, 2) void attn_kernel(
    const float* __restrict__ pos, const int* __restrict__ mask)
{
    extern __shared__ __align__(16) char sm[];
    const int qt = blockIdx.x, h = blockIdx.y, b = blockIdx.z;
    const int tid = threadIdx.x, warp = tid >> 5, lane = tid & 31;
    const int g = lane >> 2, qd = lane & 3;
    const int q0 = qt * 128;
    const uint32_t smb = smem_u32(sm);

    const size_t bh = (size_t)(b * NH + h);
    const __nv_bfloat16* Khi = g_Khi + bh * LKV * HD;
    const __nv_bfloat16* Klo = g_Klo + bh * LKV * HD;
    const __nv_bfloat16* Vhi = g_Vthi + bh * HD * LKV;
    const __nv_bfloat16* Vlo = g_Vtlo + bh * HD * LKV;

    load_tile(smb, Khi, Klo, Vhi, Vlo, 0, tid);
    asm volatile("cp.async.commit_group;" ::: "memory");

    uint32_t Qh[4][4], Ql[4][4];
    {
        const __nv_bfloat16* qh = g_Qhi + bh * LQ * HD;
        const __nv_bfloat16* ql = g_Qlo + bh * LQ * HD;
        size_t r0 = (size_t)(q0 + 16 * warp + g) * HD;
        size_t r1 = r0 + 8 * HD;
        #pragma unroll
        for (int s = 0; s < 4; s++) {
            int c = s * 16 + qd * 2;
            Qh[s][0] = *(const uint32_t*)(qh + r0 + c);
            Qh[s][1] = *(const uint32_t*)(qh + r1 + c);
            Qh[s][2] = *(const uint32_t*)(qh + r0 + c + 8);
            Qh[s][3] = *(const uint32_t*)(qh + r1 + c + 8);
            Ql[s][0] = *(const uint32_t*)(ql + r0 + c);
            Ql[s][1] = *(const uint32_t*)(ql + r1 + c);
            Ql[s][2] = *(const uint32_t*)(ql + r0 + c + 8);
            Ql[s][3] = *(const uint32_t*)(ql + r1 + c + 8);
        }
    }

    float O[8][4];
    #pragma unroll
    for (int nt = 0; nt < 8; nt++)
        #pragma unroll
        for (int j = 0; j < 4; j++) O[nt][j] = 0.f;
    float ls0 = 0.f, ls1 = 0.f;

    const float* pr0 = pos + (size_t)(h * LQ + q0 + 16 * warp + g) * LKV;
    const float* pr1 = pr0 + (size_t)8 * LKV;

    for (int t = 0; t < 64; t++) {
        const char* cur = sm + (t & 1) * STAGE;
        __syncthreads();
        if (t < 63) {
            load_tile(smb + ((t + 1) & 1) * STAGE, Khi, Klo, Vhi, Vlo, t + 1, tid);
            asm volatile("cp.async.commit_group;" ::: "memory");
            asm volatile("cp.async.wait_group 1;" ::: "memory");
        } else {
            asm volatile("cp.async.wait_group 0;" ::: "memory");
        }
        __syncthreads();

        float S[8][4];
        #pragma unroll
        for (int nt = 0; nt < 8; nt++)
            #pragma unroll
            for (int j = 0; j < 4; j++) S[nt][j] = 0.f;
        const char* Kh = cur;
        const char* Kl = cur + PL;
        #pragma unroll
        for (int s = 0; s < 4; s++) {
            uint32_t bh0, bh1, bl0, bl1;
            #pragma unroll
            for (int nt = 0; nt < 8; nt++) {
                int ko = (nt * 8 + g) * RS + (s * 16 + qd * 2) * 2;
                bh0 = *(const uint32_t*)(Kh + ko);
                bh1 = *(const uint32_t*)(Kh + ko + 16);
                bl0 = *(const uint32_t*)(Kl + ko);
                bl1 = *(const uint32_t*)(Kl + ko + 16);
                mma_bf16(S[nt], Qh[s], bh0, bh1);
                mma_bf16(S[nt], Ql[s], bh0, bh1);
                mma_bf16(S[nt], Qh[s], bl0, bl1);
            }
        }

        const char* Vh = cur + 2 * PL;
        const char* Vl = cur + 3 * PL;
        #pragma unroll
        for (int s = 0; s < 4; s++) {
            int colg = t * 64 + s * 16 + 2 * qd;
            float2 pa0 = *(const float2*)(pr0 + colg);
            float2 pb0 = *(const float2*)(pr1 + colg);
            float2 pa1 = *(const float2*)(pr0 + colg + 8);
            float2 pb1 = *(const float2*)(pr1 + colg + 8);
            float e00 = __expf(S[2*s][0]   + pa0.x - 8.f);
            float e01 = __expf(S[2*s][1]   + pa0.y - 8.f);
            float e02 = __expf(S[2*s][2]   + pb0.x - 8.f);
            float e03 = __expf(S[2*s][3]   + pb0.y - 8.f);
            float e10 = __expf(S[2*s+1][0] + pa1.x - 8.f);
            float e11 = __expf(S[2*s+1][1] + pa1.y - 8.f);
            float e12 = __expf(S[2*s+1][2] + pb1.x - 8.f);
            float e13 = __expf(S[2*s+1][3] + pb1.y - 8.f);
            ls0 += e00 + e01 + e10 + e11;
            ls1 += e02 + e03 + e12 + e13;
            uint32_t ah[4], al[4];
            float r0, r1;
            ah[0] = pack_hi(e00, e01, r0, r1); al[0] = pack_bf2(r0, r1);
            ah[1] = pack_hi(e02, e03, r0, r1); al[1] = pack_bf2(r0, r1);
            ah[2] = pack_hi(e10, e11, r0, r1); al[2] = pack_bf2(r0, r1);
            ah[3] = pack_hi(e12, e13, r0, r1); al[3] = pack_bf2(r0, r1);
            #pragma unroll
            for (int nt = 0; nt < 8; nt++) {
                int vo = (nt * 8 + g) * RS + (s * 16 + qd * 2) * 2;
                uint32_t bh0 = *(const uint32_t*)(Vh + vo);
                uint32_t bh1 = *(const uint32_t*)(Vh + vo + 16);
                uint32_t bl0 = *(const uint32_t*)(Vl + vo);
                uint32_t bl1 = *(const uint32_t*)(Vl + vo + 16);
                mma_bf16(O[nt], ah, bh0, bh1);
                mma_bf16(O[nt], al, bh0, bh1);
                mma_bf16(O[nt], ah, bl0, bl1);
            }
        }
    }

    ls0 += __shfl_xor_sync(0xffffffffu, ls0, 1);
    ls0 += __shfl_xor_sync(0xffffffffu, ls0, 2);
    ls1 += __shfl_xor_sync(0xffffffffu, ls1, 1);
    ls1 += __shfl_xor_sync(0xffffffffu, ls1, 2);

    const int row0 = 16 * warp + g;
    const int mk0 = mask[b * LQ + q0 + row0];
    const int mk1 = mask[b * LQ + q0 + row0 + 8];
    const float inv0 = (mk0 != 0 && ls0 > 0.f) ? (1.f / ls0) : 0.f;
    const float inv1 = (mk1 != 0 && ls1 > 0.f) ? (1.f / ls1) : 0.f;

    size_t o0 = (size_t)(b * LQ + q0 + row0) * E_ + h * HD;
    size_t o1 = o0 + (size_t)8 * E_;
    #pragma unroll
    for (int nt = 0; nt < 8; nt++) {
        int d = nt * 8 + qd * 2;
        float r0, r1;
        uint32_t h01 = pack_hi(O[nt][0] * inv0, O[nt][1] * inv0, r0, r1);
        *(uint32_t*)(g_ctxhi + o0 + d) = h01;
        *(uint32_t*)(g_ctxlo + o0 + d) = pack_bf2(r0, r1);
        uint32_t h23 = pack_hi(O[nt][2] * inv1, O[nt][3] * inv1, r0, r1);
        *(uint32_t*)(g_ctxhi + o1 + d) = h23;
        *(uint32_t*)(g_ctxlo + o1 + d) = pack_bf2(r0, r1);
    }
}

// ---------------------------------------------------------------------------
extern "C" void kernel_launch(void* const* d_in, const int* in_sizes, int n_in,
                              void* d_out, int out_size)
{
    const float* Xq   = (const float*)d_in[0];
    const float* Xkv  = (const float*)d_in[1];
    const int*   mask = (const int*)  d_in[2];
    const float* Wq   = (const float*)d_in[3];
    const float* bq   = (const float*)d_in[4];
    const float* Wkv  = (const float*)d_in[5];
    const float* bkv  = (const float*)d_in[6];
    const float* Wp   = (const float*)d_in[7];
    const float* bp   = (const float*)d_in[8];
    const float* pos  = (const float*)d_in[9];
    float* out = (float*)d_out;

    static int attr_set = 0;
    if (!attr_set) {
        cudaFuncSetAttribute(attn_kernel,
                             cudaFuncAttributeMaxDynamicSharedMemorySize, SMEM_ATTN);
        cudaFuncSetAttribute(qproj_kernel,
                             cudaFuncAttributeMaxDynamicSharedMemorySize, GSMEM);
        cudaFuncSetAttribute(kvproj_kernel,
                             cudaFuncAttributeMaxDynamicSharedMemorySize, GSMEM);
        cudaFuncSetAttribute(oproj_kernel,
                             cudaFuncAttributeMaxDynamicSharedMemorySize, GSMEM);
        attr_set = 1;
    }

    __nv_bfloat16 *xqh, *xql, *xkh, *xkl, *wqh, *wql, *wkh, *wkl, *wph, *wpl;
    cudaGetSymbolAddress((void**)&xqh, g_Xqhi);
    cudaGetSymbolAddress((void**)&xql, g_Xqlo);
    cudaGetSymbolAddress((void**)&xkh, g_Xkvhi);
    cudaGetSymbolAddress((void**)&xkl, g_Xkvlo);
    cudaGetSymbolAddress((void**)&wqh, g_Wqt);
    cudaGetSymbolAddress((void**)&wql, g_Wqtl);
    cudaGetSymbolAddress((void**)&wkh, g_Wkvt);
    cudaGetSymbolAddress((void**)&wkl, g_Wkvtl);
    cudaGetSymbolAddress((void**)&wph, g_Wpt);
    cudaGetSymbolAddress((void**)&wpl, g_Wptl);

    // prep: splits and transposed weight splits
    split_kernel<<<(B_ * LQ * CQ / 4 + 255) / 256, 256>>>(Xq, xqh, xql, B_ * LQ * CQ / 4);
    split_kernel<<<(B_ * LKV * CKV / 4 + 255) / 256, 256>>>(Xkv, xkh, xkl, B_ * LKV * CKV / 4);
    tsplit_kernel<<<dim3(E_ / 32, CQ / 32), 256>>>(Wq, wqh, wql, CQ, E_);
    tsplit_kernel<<<dim3(2 * E_ / 32, CKV / 32), 256>>>(Wkv, wkh, wkl, CKV, 2 * E_);
    tsplit_kernel<<<dim3(E_ / 32, E_ / 32), 256>>>(Wp, wph, wpl, E_, E_);

    // projections (split-bf16 mma)
    qproj_kernel<<<dim3(E_ / 64, B_ * LQ / 128), 256, GSMEM>>>(bq);
    kvproj_kernel<<<dim3(2 * E_ / 64, B_ * LKV / 128), 256, GSMEM>>>(bkv);
    // attention
    attn_kernel<<<dim3(LQ / 128, NH, B_), 256, SMEM_ATTN>>>(pos, mask);
    // output projection
    oproj_kernel<<<dim3(E_ / 64, B_ * LQ / 128), 256, GSMEM>>>(bp, out);
}

// round 7
// speedup vs baseline: 2.4268x; 1.1197x over previous
#include <cuda_runtime.h>
#include <cuda_bf16.h>
#include <cstdint>

// Problem constants
#define B_  4
#define LQ  1024
#define LKV 4096
#define CQ  512
#define CKV 512
#define E_  512
#define NH  8
#define HD  64
#define GK  512   // contraction dim of every projection

// ---------------------------------------------------------------------------
// Scratch (device globals — no allocation allowed). All split-bf16 planes.
// ---------------------------------------------------------------------------
__device__ __align__(256) __nv_bfloat16 g_Xqhi [B_ * LQ  * CQ];
__device__ __align__(256) __nv_bfloat16 g_Xqlo [B_ * LQ  * CQ];
__device__ __align__(256) __nv_bfloat16 g_Xkvhi[B_ * LKV * CKV];
__device__ __align__(256) __nv_bfloat16 g_Xkvlo[B_ * LKV * CKV];
__device__ __align__(256) __nv_bfloat16 g_Wqt  [E_ * CQ];        // [N,K] hi
__device__ __align__(256) __nv_bfloat16 g_Wqtl [E_ * CQ];
__device__ __align__(256) __nv_bfloat16 g_Wkvt [2 * E_ * CKV];
__device__ __align__(256) __nv_bfloat16 g_Wkvtl[2 * E_ * CKV];
__device__ __align__(256) __nv_bfloat16 g_Wpt  [E_ * E_];
__device__ __align__(256) __nv_bfloat16 g_Wptl [E_ * E_];
__device__ __align__(256) __nv_bfloat16 g_Qhi [B_ * NH * LQ  * HD];
__device__ __align__(256) __nv_bfloat16 g_Qlo [B_ * NH * LQ  * HD];
__device__ __align__(256) __nv_bfloat16 g_Khi [B_ * NH * LKV * HD];
__device__ __align__(256) __nv_bfloat16 g_Klo [B_ * NH * LKV * HD];
__device__ __align__(256) __nv_bfloat16 g_Vthi[B_ * NH * HD * LKV];  // [b,h,d,k]
__device__ __align__(256) __nv_bfloat16 g_Vtlo[B_ * NH * HD * LKV];
__device__ __align__(256) __nv_bfloat16 g_ctxhi[B_ * LQ * E_];       // [b,q,(h,d)]
__device__ __align__(256) __nv_bfloat16 g_ctxlo[B_ * LQ * E_];

// ---------------------------------------------------------------------------
// helpers
// ---------------------------------------------------------------------------
__device__ __forceinline__ uint32_t smem_u32(const void* p) {
    uint32_t a;
    asm("{ .reg .u64 t; cvta.to.shared.u64 t, %1; cvt.u32.u64 %0, t; }"
        : "=r"(a) : "l"(p));
    return a;
}
__device__ __forceinline__ void mma_bf16(float c[4], const uint32_t a[4],
                                         uint32_t b0, uint32_t b1)
{
    asm volatile(
        "mma.sync.aligned.m16n8k16.row.col.f32.bf16.bf16.f32 "
        "{%0,%1,%2,%3}, {%4,%5,%6,%7}, {%8,%9}, {%0,%1,%2,%3};\n"
        : "+f"(c[0]), "+f"(c[1]), "+f"(c[2]), "+f"(c[3])
        : "r"(a[0]), "r"(a[1]), "r"(a[2]), "r"(a[3]), "r"(b0), "r"(b1));
}
__device__ __forceinline__ void ldsm_x4(uint32_t& r0, uint32_t& r1,
                                        uint32_t& r2, uint32_t& r3,
                                        uint32_t addr)
{
    asm volatile("ldmatrix.sync.aligned.m8n8.x4.shared.b16 {%0,%1,%2,%3}, [%4];"
                 : "=r"(r0), "=r"(r1), "=r"(r2), "=r"(r3) : "r"(addr));
}
__device__ __forceinline__ uint32_t pack_hi(float v0, float v1,
                                            float& r0, float& r1)
{
    __nv_bfloat162 h = __floats2bfloat162_rn(v0, v1);
    r0 = v0 - __low2float(h);
    r1 = v1 - __high2float(h);
    return *(uint32_t*)&h;
}
__device__ __forceinline__ uint32_t pack_bf2(float v0, float v1)
{
    __nv_bfloat162 h = __floats2bfloat162_rn(v0, v1);
    return *(uint32_t*)&h;
}

// ---------------------------------------------------------------------------
// Prep kernels
// ---------------------------------------------------------------------------
__global__ __launch_bounds__(256) void split_kernel(
    const float* __restrict__ src, __nv_bfloat16* __restrict__ hi,
    __nv_bfloat16* __restrict__ lo, int n4)
{
    int i = blockIdx.x * 256 + threadIdx.x;
    if (i >= n4) return;
    float4 v = ((const float4*)src)[i];
    float r0, r1;
    uint32_t h01 = pack_hi(v.x, v.y, r0, r1);
    uint32_t l01 = pack_bf2(r0, r1);
    uint32_t h23 = pack_hi(v.z, v.w, r0, r1);
    uint32_t l23 = pack_bf2(r0, r1);
    ((uint32_t*)hi)[2 * i]     = h01;
    ((uint32_t*)hi)[2 * i + 1] = h23;
    ((uint32_t*)lo)[2 * i]     = l01;
    ((uint32_t*)lo)[2 * i + 1] = l23;
}

// Transpose + split: W [K,N] fp32 -> T [N,K] bf16 hi/lo
__global__ __launch_bounds__(256) void tsplit_kernel(
    const float* __restrict__ W, __nv_bfloat16* __restrict__ Thi,
    __nv_bfloat16* __restrict__ Tlo, int K, int N)
{
    __shared__ float Ts[32][33];
    const int k0 = blockIdx.y * 32, n0 = blockIdx.x * 32;
    const int tx = threadIdx.x & 31, ty = threadIdx.x >> 5;
    #pragma unroll
    for (int i = 0; i < 4; i++) {
        int k = ty + i * 8;
        Ts[k][tx] = W[(size_t)(k0 + k) * N + n0 + tx];
    }
    __syncthreads();
    #pragma unroll
    for (int i = 0; i < 4; i++) {
        int nr = ty + i * 8;
        float v = Ts[tx][nr];
        __nv_bfloat16 h = __float2bfloat16_rn(v);
        size_t o = (size_t)(n0 + nr) * K + k0 + tx;
        Thi[o] = h;
        Tlo[o] = __float2bfloat16_rn(v - __bfloat162float(h));
    }
}

// ---------------------------------------------------------------------------
// Split-bf16 mma GEMM core with ldmatrix fragment loads.
// C[M,N] = A[M,K] * Bt[N,K]^T, K=512. CTA 256 thr / 8 warps, tile 128x64,
// K-chunks of 64, cp.async double-buffered.
// ---------------------------------------------------------------------------
#define GRS    144
#define GA_PL  (128 * GRS)
#define GB_PL  (64 * GRS)
#define GSTAGE (2 * GA_PL + 2 * GB_PL)
#define GSMEM  (2 * GSTAGE)

__device__ __forceinline__ void gload(
    uint32_t sdst,
    const __nv_bfloat16* Ahi, const __nv_bfloat16* Alo,
    const __nv_bfloat16* Bthi, const __nv_bfloat16* Btlo,
    int m0, int n0, int c, int tid)
{
    #pragma unroll
    for (int i = 0; i < 12; i++) {
        int idx = tid + i * 256;
        uint32_t dst;
        const __nv_bfloat16* src;
        if (i < 8) {
            int p = idx >> 10;
            int r = (idx & 1023) >> 3, c16 = idx & 7;
            dst = sdst + p * GA_PL + r * GRS + c16 * 16;
            src = (p ? Alo : Ahi) + (size_t)(m0 + r) * GK + c * 64 + c16 * 8;
        } else {
            int j = idx - 2048;
            int p = j >> 9;
            int r = (j & 511) >> 3, c16 = j & 7;
            dst = sdst + 2 * GA_PL + p * GB_PL + r * GRS + c16 * 16;
            src = (p ? Btlo : Bthi) + (size_t)(n0 + r) * GK + c * 64 + c16 * 8;
        }
        asm volatile("cp.async.cg.shared.global [%0], [%1], 16;"
                     :: "r"(dst), "l"(src));
    }
}

__device__ __forceinline__ void gemm_mma_core(
    const __nv_bfloat16* Ahi, const __nv_bfloat16* Alo,
    const __nv_bfloat16* Bthi, const __nv_bfloat16* Btlo,
    int m0, int n0, char* sm, int tid, float (&S)[8][4])
{
    const uint32_t smb = smem_u32(sm);
    const int warp = tid >> 5, lane = tid & 31;
    const int lr = lane & 7;
    // ldmatrix lane->address offsets (bytes within a plane)
    const uint32_t aoff = (uint32_t)((16 * warp + ((lane >> 3) & 1) * 8 + lr) * GRS
                                     + ((lane >> 4) & 1) * 16);
    const uint32_t boff = (uint32_t)((((lane >> 4) & 1) * 8 + lr) * GRS
                                     + ((lane >> 3) & 1) * 16);

    #pragma unroll
    for (int nt = 0; nt < 8; nt++)
        #pragma unroll
        for (int j = 0; j < 4; j++) S[nt][j] = 0.f;

    gload(smb, Ahi, Alo, Bthi, Btlo, m0, n0, 0, tid);
    asm volatile("cp.async.commit_group;" ::: "memory");

    for (int c = 0; c < 8; c++) {
        const uint32_t cur = smb + (c & 1) * GSTAGE;
        __syncthreads();
        if (c < 7) {
            gload(smb + ((c + 1) & 1) * GSTAGE, Ahi, Alo, Bthi, Btlo,
                  m0, n0, c + 1, tid);
            asm volatile("cp.async.commit_group;" ::: "memory");
            asm volatile("cp.async.wait_group 1;" ::: "memory");
        } else {
            asm volatile("cp.async.wait_group 0;" ::: "memory");
        }
        __syncthreads();

        const uint32_t Ah = cur + aoff;
        const uint32_t Al = Ah + GA_PL;
        const uint32_t Bh = cur + 2 * GA_PL + boff;
        const uint32_t Bl = Bh + GB_PL;
        #pragma unroll
        for (int s = 0; s < 4; s++) {
            uint32_t af[4], alf[4];
            ldsm_x4(af[0],  af[1],  af[2],  af[3],  Ah + s * 32);
            ldsm_x4(alf[0], alf[1], alf[2], alf[3], Al + s * 32);
            #pragma unroll
            for (int nt = 0; nt < 8; nt += 2) {
                uint32_t b0, b1, b2, b3, c0, c1, c2, c3;
                ldsm_x4(b0, b1, b2, b3, Bh + nt * 8 * GRS + s * 32);
                ldsm_x4(c0, c1, c2, c3, Bl + nt * 8 * GRS + s * 32);
                mma_bf16(S[nt],     af,  b0, b1);
                mma_bf16(S[nt],     alf, b0, b1);
                mma_bf16(S[nt],     af,  c0, c1);
                mma_bf16(S[nt + 1], af,  b2, b3);
                mma_bf16(S[nt + 1], alf, b2, b3);
                mma_bf16(S[nt + 1], af,  c2, c3);
            }
        }
    }
}

// ----------------------- Kernel 1: Q projection ----------------------------
__global__ __launch_bounds__(256, 2) void qproj_kernel(
    const float* __restrict__ bias)
{
    extern __shared__ __align__(16) char sm[];
    const int m0 = blockIdx.y * 128, n0 = blockIdx.x * 64;
    const int tid = threadIdx.x, warp = tid >> 5, lane = tid & 31;
    const int g = lane >> 2, qd = lane & 3;
    float S[8][4];
    gemm_mma_core(g_Xqhi, g_Xqlo, g_Wqt, g_Wqtl, m0, n0, sm, tid, S);

    const float scale = 0.125f;
    const int h = n0 >> 6;
    const int r0 = m0 + 16 * warp + g, r1 = r0 + 8;
    const int b0 = r0 >> 10, q0 = r0 & 1023;
    const int b1 = r1 >> 10, q1 = r1 & 1023;
    size_t ro0 = ((size_t)(b0 * NH + h) * LQ + q0) * HD;
    size_t ro1 = ((size_t)(b1 * NH + h) * LQ + q1) * HD;
    #pragma unroll
    for (int nt = 0; nt < 8; nt++) {
        int n = n0 + nt * 8 + qd * 2;
        int d = n & 63;
        float v0 = (S[nt][0] + bias[n])     * scale;
        float v1 = (S[nt][1] + bias[n + 1]) * scale;
        float v2 = (S[nt][2] + bias[n])     * scale;
        float v3 = (S[nt][3] + bias[n + 1]) * scale;
        float r0f, r1f;
        uint32_t h01 = pack_hi(v0, v1, r0f, r1f);
        *(uint32_t*)(g_Qhi + ro0 + d) = h01;
        *(uint32_t*)(g_Qlo + ro0 + d) = pack_bf2(r0f, r1f);
        uint32_t h23 = pack_hi(v2, v3, r0f, r1f);
        *(uint32_t*)(g_Qhi + ro1 + d) = h23;
        *(uint32_t*)(g_Qlo + ro1 + d) = pack_bf2(r0f, r1f);
    }
}

// ----------------------- Kernel 2: KV projection ---------------------------
__global__ __launch_bounds__(256, 2) void kvproj_kernel(
    const float* __restrict__ bias)
{
    extern __shared__ __align__(16) char sm[];
    const int m0 = blockIdx.y * 128, n0 = blockIdx.x * 64;
    const int tid = threadIdx.x, warp = tid >> 5, lane = tid & 31;
    const int g = lane >> 2, qd = lane & 3;
    float S[8][4];
    gemm_mma_core(g_Xkvhi, g_Xkvlo, g_Wkvt, g_Wkvtl, m0, n0, sm, tid, S);

    const int bb = m0 >> 12;
    if (n0 < 512) {
        const int h = n0 >> 6;
        const int k0r = (m0 + 16 * warp + g) & 4095;
        size_t ro0 = ((size_t)(bb * NH + h) * LKV + k0r) * HD;
        size_t ro1 = ro0 + (size_t)8 * HD;
        #pragma unroll
        for (int nt = 0; nt < 8; nt++) {
            int n = n0 + nt * 8 + qd * 2;
            int d = n & 63;
            float v0 = S[nt][0] + bias[n];
            float v1 = S[nt][1] + bias[n + 1];
            float v2 = S[nt][2] + bias[n];
            float v3 = S[nt][3] + bias[n + 1];
            float r0f, r1f;
            uint32_t h01 = pack_hi(v0, v1, r0f, r1f);
            *(uint32_t*)(g_Khi + ro0 + d) = h01;
            *(uint32_t*)(g_Klo + ro0 + d) = pack_bf2(r0f, r1f);
            uint32_t h23 = pack_hi(v2, v3, r0f, r1f);
            *(uint32_t*)(g_Khi + ro1 + d) = h23;
            *(uint32_t*)(g_Klo + ro1 + d) = pack_bf2(r0f, r1f);
        }
    } else {
        const int h = (n0 >> 6) & 7;
        const int key0 = m0 & 4095;
        float (*Tr)[132] = (float (*)[132])sm;
        __syncthreads();
        const int kr0 = 16 * warp + g, kr1 = kr0 + 8;
        #pragma unroll
        for (int nt = 0; nt < 8; nt++) {
            int n = n0 + nt * 8 + qd * 2;
            int d = n & 63;
            Tr[d][kr0]     = S[nt][0] + bias[n];
            Tr[d + 1][kr0] = S[nt][1] + bias[n + 1];
            Tr[d][kr1]     = S[nt][2] + bias[n];
            Tr[d + 1][kr1] = S[nt][3] + bias[n + 1];
        }
        __syncthreads();
        #pragma unroll
        for (int it = 0; it < 16; it++) {
            int idx = tid + it * 256;
            int d = idx >> 6, kp = (idx & 63) * 2;
            float v0 = Tr[d][kp], v1 = Tr[d][kp + 1];
            float r0f, r1f;
            uint32_t hv = pack_hi(v0, v1, r0f, r1f);
            size_t ro = ((size_t)(bb * NH + h) * HD + d) * LKV + key0 + kp;
            *(uint32_t*)(g_Vthi + ro) = hv;
            *(uint32_t*)(g_Vtlo + ro) = pack_bf2(r0f, r1f);
        }
    }
}

// ----------------------- Kernel 4: output projection -----------------------
__global__ __launch_bounds__(256, 2) void oproj_kernel(
    const float* __restrict__ bias, float* __restrict__ out)
{
    extern __shared__ __align__(16) char sm[];
    const int m0 = blockIdx.y * 128, n0 = blockIdx.x * 64;
    const int tid = threadIdx.x, warp = tid >> 5, lane = tid & 31;
    const int g = lane >> 2, qd = lane & 3;
    float S[8][4];
    gemm_mma_core(g_ctxhi, g_ctxlo, g_Wpt, g_Wptl, m0, n0, sm, tid, S);

    const int r0 = m0 + 16 * warp + g, r1 = r0 + 8;
    #pragma unroll
    for (int nt = 0; nt < 8; nt++) {
        int n = n0 + nt * 8 + qd * 2;
        float b0v = bias[n], b1v = bias[n + 1];
        *(float2*)(out + (size_t)r0 * E_ + n) = make_float2(S[nt][0] + b0v, S[nt][1] + b1v);
        *(float2*)(out + (size_t)r1 * E_ + n) = make_float2(S[nt][2] + b0v, S[nt][3] + b1v);
    }
}

// ---------------------------------------------------------------------------
// Attention: split-bf16 3-term mma flash, register P, ldmatrix B-fragments
// ---------------------------------------------------------------------------
#define RS    144
#define PL    (64 * RS)
#define STAGE (4 * PL)
#define SMEM_ATTN (2 * STAGE)

__device__ __forceinline__ void load_tile(
    uint32_t sdst,
    const __nv_bfloat16* Khi, const __nv_bfloat16* Klo,
    const __nv_bfloat16* Vhi, const __nv_bfloat16* Vlo,
    int t, int tid)
{
    #pragma unroll
    for (int i = 0; i < 8; i++) {
        int c = tid + i * 256;
        int p = i >> 1;
        int cc = c & 511, row = cc >> 3, c16 = cc & 7;
        uint32_t dst = sdst + p * PL + row * RS + c16 * 16;
        const __nv_bfloat16* src;
        if (p == 0)      src = Khi + (size_t)(t * 64 + row) * HD + c16 * 8;
        else if (p == 1) src = Klo + (size_t)(t * 64 + row) * HD + c16 * 8;
        else if (p == 2) src = Vhi + (size_t)row * LKV + t * 64 + c16 * 8;
        else             src = Vlo + (size_t)row * LKV + t * 64 + c16 * 8;
        asm volatile("cp.async.cg.shared.global [%0], [%1], 16;"
                     :: "r"(dst), "l"(src));
    }
}

__global__ __launch_bounds__(256, 2) void attn_kernel(
    const float* __restrict__ pos, const int* __restrict__ mask)
{
    extern __shared__ __align__(16) char sm[];
    const int qt = blockIdx.x, h = blockIdx.y, b = blockIdx.z;
    const int tid = threadIdx.x, warp = tid >> 5, lane = tid & 31;
    const int g = lane >> 2, qd = lane & 3;
    const int lr = lane & 7;
    const int q0 = qt * 128;
    const uint32_t smb = smem_u32(sm);
    const uint32_t boff = (uint32_t)((((lane >> 4) & 1) * 8 + lr) * RS
                                     + ((lane >> 3) & 1) * 16);

    const size_t bh = (size_t)(b * NH + h);
    const __nv_bfloat16* Khi = g_Khi + bh * LKV * HD;
    const __nv_bfloat16* Klo = g_Klo + bh * LKV * HD;
    const __nv_bfloat16* Vhi = g_Vthi + bh * HD * LKV;
    const __nv_bfloat16* Vlo = g_Vtlo + bh * HD * LKV;

    load_tile(smb, Khi, Klo, Vhi, Vlo, 0, tid);
    asm volatile("cp.async.commit_group;" ::: "memory");

    uint32_t Qh[4][4], Ql[4][4];
    {
        const __nv_bfloat16* qh = g_Qhi + bh * LQ * HD;
        const __nv_bfloat16* ql = g_Qlo + bh * LQ * HD;
        size_t r0 = (size_t)(q0 + 16 * warp + g) * HD;
        size_t r1 = r0 + 8 * HD;
        #pragma unroll
        for (int s = 0; s < 4; s++) {
            int c = s * 16 + qd * 2;
            Qh[s][0] = *(const uint32_t*)(qh + r0 + c);
            Qh[s][1] = *(const uint32_t*)(qh + r1 + c);
            Qh[s][2] = *(const uint32_t*)(qh + r0 + c + 8);
            Qh[s][3] = *(const uint32_t*)(qh + r1 + c + 8);
            Ql[s][0] = *(const uint32_t*)(ql + r0 + c);
            Ql[s][1] = *(const uint32_t*)(ql + r1 + c);
            Ql[s][2] = *(const uint32_t*)(ql + r0 + c + 8);
            Ql[s][3] = *(const uint32_t*)(ql + r1 + c + 8);
        }
    }

    float O[8][4];
    #pragma unroll
    for (int nt = 0; nt < 8; nt++)
        #pragma unroll
        for (int j = 0; j < 4; j++) O[nt][j] = 0.f;
    float ls0 = 0.f, ls1 = 0.f;

    const float* pr0 = pos + (size_t)(h * LQ + q0 + 16 * warp + g) * LKV;
    const float* pr1 = pr0 + (size_t)8 * LKV;

    for (int t = 0; t < 64; t++) {
        const uint32_t cur = smb + (t & 1) * STAGE;
        __syncthreads();
        if (t < 63) {
            load_tile(smb + ((t + 1) & 1) * STAGE, Khi, Klo, Vhi, Vlo, t + 1, tid);
            asm volatile("cp.async.commit_group;" ::: "memory");
            asm volatile("cp.async.wait_group 1;" ::: "memory");
        } else {
            asm volatile("cp.async.wait_group 0;" ::: "memory");
        }
        __syncthreads();

        // ---- S = Q K^T (3-term split, ldmatrix B) ----
        float S[8][4];
        #pragma unroll
        for (int nt = 0; nt < 8; nt++)
            #pragma unroll
            for (int j = 0; j < 4; j++) S[nt][j] = 0.f;
        const uint32_t Kh = cur + boff;
        const uint32_t Kl = Kh + PL;
        #pragma unroll
        for (int s = 0; s < 4; s++) {
            #pragma unroll
            for (int nt = 0; nt < 8; nt += 2) {
                uint32_t b0, b1, b2, b3, c0, c1, c2, c3;
                ldsm_x4(b0, b1, b2, b3, Kh + nt * 8 * RS + s * 32);
                ldsm_x4(c0, c1, c2, c3, Kl + nt * 8 * RS + s * 32);
                mma_bf16(S[nt],     Qh[s], b0, b1);
                mma_bf16(S[nt],     Ql[s], b0, b1);
                mma_bf16(S[nt],     Qh[s], c0, c1);
                mma_bf16(S[nt + 1], Qh[s], b2, b3);
                mma_bf16(S[nt + 1], Ql[s], b2, b3);
                mma_bf16(S[nt + 1], Qh[s], c2, c3);
            }
        }

        // ---- exp + pack (register P) fused with PV per k-chunk s ----
        const uint32_t Vh = cur + 2 * PL + boff;
        const uint32_t Vl = Vh + PL;
        #pragma unroll
        for (int s = 0; s < 4; s++) {
            int colg = t * 64 + s * 16 + 2 * qd;
            float2 pa0 = *(const float2*)(pr0 + colg);
            float2 pb0 = *(const float2*)(pr1 + colg);
            float2 pa1 = *(const float2*)(pr0 + colg + 8);
            float2 pb1 = *(const float2*)(pr1 + colg + 8);
            float e00 = __expf(S[2*s][0]   + pa0.x - 8.f);
            float e01 = __expf(S[2*s][1]   + pa0.y - 8.f);
            float e02 = __expf(S[2*s][2]   + pb0.x - 8.f);
            float e03 = __expf(S[2*s][3]   + pb0.y - 8.f);
            float e10 = __expf(S[2*s+1][0] + pa1.x - 8.f);
            float e11 = __expf(S[2*s+1][1] + pa1.y - 8.f);
            float e12 = __expf(S[2*s+1][2] + pb1.x - 8.f);
            float e13 = __expf(S[2*s+1][3] + pb1.y - 8.f);
            ls0 += e00 + e01 + e10 + e11;
            ls1 += e02 + e03 + e12 + e13;
            uint32_t ah[4], al[4];
            float r0, r1;
            ah[0] = pack_hi(e00, e01, r0, r1); al[0] = pack_bf2(r0, r1);
            ah[1] = pack_hi(e02, e03, r0, r1); al[1] = pack_bf2(r0, r1);
            ah[2] = pack_hi(e10, e11, r0, r1); al[2] = pack_bf2(r0, r1);
            ah[3] = pack_hi(e12, e13, r0, r1); al[3] = pack_bf2(r0, r1);
            #pragma unroll
            for (int nt = 0; nt < 8; nt += 2) {
                uint32_t b0, b1, b2, b3, c0, c1, c2, c3;
                ldsm_x4(b0, b1, b2, b3, Vh + nt * 8 * RS + s * 32);
                ldsm_x4(c0, c1, c2, c3, Vl + nt * 8 * RS + s * 32);
                mma_bf16(O[nt],     ah, b0, b1);
                mma_bf16(O[nt],     al, b0, b1);
                mma_bf16(O[nt],     ah, c0, c1);
                mma_bf16(O[nt + 1], ah, b2, b3);
                mma_bf16(O[nt + 1], al, b2, b3);
                mma_bf16(O[nt + 1], ah, c2, c3);
            }
        }
    }

    ls0 += __shfl_xor_sync(0xffffffffu, ls0, 1);
    ls0 += __shfl_xor_sync(0xffffffffu, ls0, 2);
    ls1 += __shfl_xor_sync(0xffffffffu, ls1, 1);
    ls1 += __shfl_xor_sync(0xffffffffu, ls1, 2);

    const int row0 = 16 * warp + g;
    const int mk0 = mask[b * LQ + q0 + row0];
    const int mk1 = mask[b * LQ + q0 + row0 + 8];
    const float inv0 = (mk0 != 0 && ls0 > 0.f) ? (1.f / ls0) : 0.f;
    const float inv1 = (mk1 != 0 && ls1 > 0.f) ? (1.f / ls1) : 0.f;

    size_t o0 = (size_t)(b * LQ + q0 + row0) * E_ + h * HD;
    size_t o1 = o0 + (size_t)8 * E_;
    #pragma unroll
    for (int nt = 0; nt < 8; nt++) {
        int d = nt * 8 + qd * 2;
        float r0, r1;
        uint32_t h01 = pack_hi(O[nt][0] * inv0, O[nt][1] * inv0, r0, r1);
        *(uint32_t*)(g_ctxhi + o0 + d) = h01;
        *(uint32_t*)(g_ctxlo + o0 + d) = pack_bf2(r0, r1);
        uint32_t h23 = pack_hi(O[nt][2] * inv1, O[nt][3] * inv1, r0, r1);
        *(uint32_t*)(g_ctxhi + o1 + d) = h23;
        *(uint32_t*)(g_ctxlo + o1 + d) = pack_bf2(r0, r1);
    }
}

// ---------------------------------------------------------------------------
extern "C" void kernel_launch(void* const* d_in, const int* in_sizes, int n_in,
                              void* d_out, int out_size)
{
    const float* Xq   = (const float*)d_in[0];
    const float* Xkv  = (const float*)d_in[1];
    const int*   mask = (const int*)  d_in[2];
    const float* Wq   = (const float*)d_in[3];
    const float* bq   = (const float*)d_in[4];
    const float* Wkv  = (const float*)d_in[5];
    const float* bkv  = (const float*)d_in[6];
    const float* Wp   = (const float*)d_in[7];
    const float* bp   = (const float*)d_in[8];
    const float* pos  = (const float*)d_in[9];
    float* out = (float*)d_out;

    static int attr_set = 0;
    if (!attr_set) {
        cudaFuncSetAttribute(attn_kernel,
                             cudaFuncAttributeMaxDynamicSharedMemorySize, SMEM_ATTN);
        cudaFuncSetAttribute(qproj_kernel,
                             cudaFuncAttributeMaxDynamicSharedMemorySize, GSMEM);
        cudaFuncSetAttribute(kvproj_kernel,
                             cudaFuncAttributeMaxDynamicSharedMemorySize, GSMEM);
        cudaFuncSetAttribute(oproj_kernel,
                             cudaFuncAttributeMaxDynamicSharedMemorySize, GSMEM);
        attr_set = 1;
    }

    __nv_bfloat16 *xqh, *xql, *xkh, *xkl, *wqh, *wql, *wkh, *wkl, *wph, *wpl;
    cudaGetSymbolAddress((void**)&xqh, g_Xqhi);
    cudaGetSymbolAddress((void**)&xql, g_Xqlo);
    cudaGetSymbolAddress((void**)&xkh, g_Xkvhi);
    cudaGetSymbolAddress((void**)&xkl, g_Xkvlo);
    cudaGetSymbolAddress((void**)&wqh, g_Wqt);
    cudaGetSymbolAddress((void**)&wql, g_Wqtl);
    cudaGetSymbolAddress((void**)&wkh, g_Wkvt);
    cudaGetSymbolAddress((void**)&wkl, g_Wkvtl);
    cudaGetSymbolAddress((void**)&wph, g_Wpt);
    cudaGetSymbolAddress((void**)&wpl, g_Wptl);

    split_kernel<<<(B_ * LQ * CQ / 4 + 255) / 256, 256>>>(Xq, xqh, xql, B_ * LQ * CQ / 4);
    split_kernel<<<(B_ * LKV * CKV / 4 + 255) / 256, 256>>>(Xkv, xkh, xkl, B_ * LKV * CKV / 4);
    tsplit_kernel<<<dim3(E_ / 32, CQ / 32), 256>>>(Wq, wqh, wql, CQ, E_);
    tsplit_kernel<<<dim3(2 * E_ / 32, CKV / 32), 256>>>(Wkv, wkh, wkl, CKV, 2 * E_);
    tsplit_kernel<<<dim3(E_ / 32, E_ / 32), 256>>>(Wp, wph, wpl, E_, E_);

    qproj_kernel<<<dim3(E_ / 64, B_ * LQ / 128), 256, GSMEM>>>(bq);
    kvproj_kernel<<<dim3(2 * E_ / 64, B_ * LKV / 128), 256, GSMEM>>>(bkv);
    attn_kernel<<<dim3(LQ / 128, NH, B_), 256, SMEM_ATTN>>>(pos, mask);
    oproj_kernel<<<dim3(E_ / 64, B_ * LQ / 128), 256, GSMEM>>>(bp, out);
}